// round 7
// baseline (speedup 1.0000x reference)
#include <cuda_runtime.h>
#include <cuda_bf16.h>
#include <stdint.h>
#include <math.h>

// Fixed problem dims
#define NB   8
#define SEQB 2048
#define DIMQ 1024

static constexpr size_t XE = (size_t)NB * SEQB * DIMQ;   // 16,777,216
static constexpr size_t WE = (size_t)DIMQ * DIMQ;        // 1,048,576
static constexpr size_t SE = (size_t)NB * SEQB * SEQB;   // 33,554,432

// Scratch (__device__ globals: allocation-free rule)
__device__ __nv_bfloat16 g_xhi[XE],  g_xlo[XE];
__device__ __nv_bfloat16 g_wqhi[WE], g_wqlo[WE];
__device__ __nv_bfloat16 g_wkhi[WE], g_wklo[WE];
__device__ __nv_bfloat16 g_wvhi[WE], g_wvlo[WE];
__device__ __nv_bfloat16 g_Qhi[XE],  g_Qlo[XE];
__device__ __nv_bfloat16 g_Khi[XE],  g_Klo[XE];
__device__ __nv_bfloat16 g_Vthi[XE], g_Vtlo[XE];
__device__ float         g_S[SE];
__device__ __nv_bfloat16 g_Phi[SE],  g_Plo[SE];

// ---------------------------------------------------------------------------
// PTX helpers (baseline PTX only — no 'a'-gated features)
// ---------------------------------------------------------------------------
__device__ __forceinline__ uint32_t smem_u32(const void* p) {
    uint32_t a;
    asm("{ .reg .u64 t; cvta.to.shared.u64 t, %1; cvt.u32.u64 %0, t; }"
        : "=r"(a) : "l"(p));
    return a;
}

__device__ __forceinline__ void ldsm_x4(uint32_t addr, uint32_t& r0, uint32_t& r1,
                                        uint32_t& r2, uint32_t& r3) {
    asm volatile("ldmatrix.sync.aligned.m8n8.x4.shared.b16 {%0,%1,%2,%3}, [%4];"
                 : "=r"(r0), "=r"(r1), "=r"(r2), "=r"(r3) : "r"(addr));
}

__device__ __forceinline__ void mma16816(float& d0, float& d1, float& d2, float& d3,
                                         uint32_t a0, uint32_t a1, uint32_t a2, uint32_t a3,
                                         uint32_t b0, uint32_t b1) {
    asm volatile(
        "mma.sync.aligned.m16n8k16.row.col.f32.bf16.bf16.f32 "
        "{%0,%1,%2,%3}, {%4,%5,%6,%7}, {%8,%9}, {%0,%1,%2,%3};"
        : "+f"(d0), "+f"(d1), "+f"(d2), "+f"(d3)
        : "r"(a0), "r"(a1), "r"(a2), "r"(a3), "r"(b0), "r"(b1));
}

// ---------------------------------------------------------------------------
// GEMM-NT core: C[256,128] tile at (m0,n0) = sum_k A[m,k]*B[n,k], K = kb*64,
// as AhiBhi + AloBhi + AhiBlo (3 K-passes, fp32 accum in registers).
// mode 0: write fp32*alpha; mode 1: write split hi/lo bf16.
// 256 threads = 8 warps (4m x 2n), warp tile 64x64, BK=64 bf16, SW128 smem.
// 3-stage cp.async ring. 1 CTA/SM (smem 144KB, ~200 regs).
// ---------------------------------------------------------------------------
#define STAGES   3
#define STAGE_A  32768                               // 256 rows x 128B
#define STAGE_B2 16384                               // 128 rows x 128B
#define SMEM_SZ  (STAGES * (STAGE_A + STAGE_B2))     // 147456

__device__ __forceinline__ void gemm256_nt(
    const __nv_bfloat16* __restrict__ Ahi, const __nv_bfloat16* __restrict__ Alo,
    const __nv_bfloat16* __restrict__ Bhi, const __nv_bfloat16* __restrict__ Blo,
    int lda, int ldb, int kb, int m0, int n0, int ldc,
    float* __restrict__ C32,
    __nv_bfloat16* __restrict__ Chi, __nv_bfloat16* __restrict__ Clo,
    float alpha, int mode)
{
    extern __shared__ char smem[];
    const uint32_t sbase  = smem_u32(smem);
    const uint32_t sbaseB = sbase + STAGES * STAGE_A;
    const int tid  = threadIdx.x;
    const int wid  = tid >> 5;
    const int lane = tid & 31;
    const int wm = wid >> 1;      // 0..3  (64-row slab)
    const int wn = wid & 1;       // 0..1  (64-col slab)

    const int nc = 3 * kb;

    auto load_chunk = [&](int c, int s) {
        int p  = (c >= kb) + (c >= 2 * kb);
        int k0 = (c - p * kb) * 64;
        const __nv_bfloat16* As = (p == 1) ? Alo : Ahi;
        const __nv_bfloat16* Bs = (p == 2) ? Blo : Bhi;
        uint32_t aS = sbase  + s * STAGE_A;
        uint32_t bS = sbaseB + s * STAGE_B2;
#pragma unroll
        for (int i = 0; i < 8; i++) {                 // A: 256 rows x 8 x 16B
            int o = tid + i * 256;                    // 0..2047
            int row = o >> 3, seg = o & 7;
            uint32_t off = (uint32_t)(o << 4);
            uint32_t sw = off ^ ((off >> 3) & 0x70);
            const __nv_bfloat16* ga = As + (size_t)(m0 + row) * lda + k0 + seg * 8;
            asm volatile("cp.async.cg.shared.global [%0], [%1], 16;" :: "r"(aS + sw), "l"(ga));
        }
#pragma unroll
        for (int i = 0; i < 4; i++) {                 // B: 128 rows x 8 x 16B
            int o = tid + i * 256;                    // 0..1023
            int row = o >> 3, seg = o & 7;
            uint32_t off = (uint32_t)(o << 4);
            uint32_t sw = off ^ ((off >> 3) & 0x70);
            const __nv_bfloat16* gb = Bs + (size_t)(n0 + row) * ldb + k0 + seg * 8;
            asm volatile("cp.async.cg.shared.global [%0], [%1], 16;" :: "r"(bS + sw), "l"(gb));
        }
        asm volatile("cp.async.commit_group;" ::: "memory");
    };

    float acc[4][8][4];
#pragma unroll
    for (int i = 0; i < 4; i++)
#pragma unroll
        for (int j = 0; j < 8; j++)
#pragma unroll
            for (int k = 0; k < 4; k++) acc[i][j][k] = 0.f;

    // Prologue: 2 chunks in flight (nc >= 12 always here)
    load_chunk(0, 0);
    load_chunk(1, 1);

    const int lrow = lane & 15;
    const int lhi  = (lane >> 4) & 1;

    for (int c = 0; c < nc; c++) {
        const int s = c % STAGES;
        asm volatile("cp.async.wait_group 1;" ::: "memory");   // chunk c resident
        __syncthreads();

        const int nxt = c + 2;
        if (nxt < nc) load_chunk(nxt, nxt % STAGES);
        else asm volatile("cp.async.commit_group;" ::: "memory");  // keep counts uniform

        const uint32_t aS = sbase  + s * STAGE_A;
        const uint32_t bS = sbaseB + s * STAGE_B2;
#pragma unroll
        for (int kk = 0; kk < 4; kk++) {
            uint32_t a[4][4], b[4][4];
            const uint32_t col = (uint32_t)(kk * 32 + lhi * 16);   // byte offset
#pragma unroll
            for (int mf = 0; mf < 4; mf++) {
                int row = wm * 64 + mf * 16 + lrow;
                uint32_t addr = aS + row * 128 + (col ^ ((row & 7) << 4));
                ldsm_x4(addr, a[mf][0], a[mf][1], a[mf][2], a[mf][3]);
            }
#pragma unroll
            for (int nf2 = 0; nf2 < 4; nf2++) {
                int row = wn * 64 + nf2 * 16 + lrow;
                uint32_t addr = bS + row * 128 + (col ^ ((row & 7) << 4));
                ldsm_x4(addr, b[nf2][0], b[nf2][1], b[nf2][2], b[nf2][3]);
            }
#pragma unroll
            for (int mf = 0; mf < 4; mf++)
#pragma unroll
                for (int nf = 0; nf < 8; nf++) {
                    uint32_t bb0 = (nf & 1) ? b[nf >> 1][1] : b[nf >> 1][0];
                    uint32_t bb1 = (nf & 1) ? b[nf >> 1][3] : b[nf >> 1][2];
                    mma16816(acc[mf][nf][0], acc[mf][nf][1], acc[mf][nf][2], acc[mf][nf][3],
                             a[mf][0], a[mf][1], a[mf][2], a[mf][3], bb0, bb1);
                }
        }
    }

    // Epilogue: straight from registers.
#pragma unroll
    for (int mf = 0; mf < 4; mf++) {
#pragma unroll
        for (int nf = 0; nf < 8; nf++) {
            const int r0  = m0 + wm * 64 + mf * 16 + (lane >> 2);
            const int col = n0 + wn * 64 + nf * 8 + (lane & 3) * 2;
            float d0 = acc[mf][nf][0], d1 = acc[mf][nf][1];
            float d2 = acc[mf][nf][2], d3 = acc[mf][nf][3];
            if (mode == 0) {
                float2 u, v;
                u.x = d0 * alpha; u.y = d1 * alpha;
                v.x = d2 * alpha; v.y = d3 * alpha;
                *(float2*)(C32 + (size_t)r0 * ldc + col)       = u;
                *(float2*)(C32 + (size_t)(r0 + 8) * ldc + col) = v;
            } else {
                float f[4] = {d0, d1, d2, d3};
                unsigned short hs[4], ls[4];
#pragma unroll
                for (int k = 0; k < 4; k++) {
                    __nv_bfloat16 h = __float2bfloat16(f[k]);
                    __nv_bfloat16 l = __float2bfloat16(f[k] - __bfloat162float(h));
                    hs[k] = __bfloat16_as_ushort(h);
                    ls[k] = __bfloat16_as_ushort(l);
                }
                *(uint32_t*)(Chi + (size_t)r0 * ldc + col)       = hs[0] | ((uint32_t)hs[1] << 16);
                *(uint32_t*)(Chi + (size_t)(r0 + 8) * ldc + col) = hs[2] | ((uint32_t)hs[3] << 16);
                *(uint32_t*)(Clo + (size_t)r0 * ldc + col)       = ls[0] | ((uint32_t)ls[1] << 16);
                *(uint32_t*)(Clo + (size_t)(r0 + 8) * ldc + col) = ls[2] | ((uint32_t)ls[3] << 16);
            }
        }
    }
}

// ---------------------------------------------------------------------------
// Conversion kernels: fp32 -> bf16 hi/lo split
// ---------------------------------------------------------------------------
__device__ __forceinline__ void split4_store(float4 v, __nv_bfloat16* dh, __nv_bfloat16* dl, size_t i) {
    float f[4] = {v.x, v.y, v.z, v.w};
    unsigned short hs[4], ls[4];
#pragma unroll
    for (int k = 0; k < 4; k++) {
        __nv_bfloat16 h = __float2bfloat16(f[k]);
        __nv_bfloat16 l = __float2bfloat16(f[k] - __bfloat162float(h));
        hs[k] = __bfloat16_as_ushort(h);
        ls[k] = __bfloat16_as_ushort(l);
    }
    *(uint2*)(dh + i) = make_uint2(hs[0] | ((uint32_t)hs[1] << 16), hs[2] | ((uint32_t)hs[3] << 16));
    *(uint2*)(dl + i) = make_uint2(ls[0] | ((uint32_t)ls[1] << 16), ls[2] | ((uint32_t)ls[3] << 16));
}

__global__ __launch_bounds__(256) void k_conv_x(const float* __restrict__ x) {
    size_t i = ((size_t)blockIdx.x * 256 + threadIdx.x) * 4;
    split4_store(*(const float4*)(x + i), g_xhi, g_xlo, i);
}

__global__ __launch_bounds__(256) void k_conv_w(const float* __restrict__ Wq,
                                                const float* __restrict__ Wk,
                                                const float* __restrict__ Wv) {
    const int z = blockIdx.z;
    const float* src = (z == 0) ? Wq : (z == 1) ? Wk : Wv;
    __nv_bfloat16* dh = (z == 0) ? g_wqhi : (z == 1) ? g_wkhi : g_wvhi;
    __nv_bfloat16* dl = (z == 0) ? g_wqlo : (z == 1) ? g_wklo : g_wvlo;
    size_t i = ((size_t)blockIdx.x * 256 + threadIdx.x) * 4;
    split4_store(*(const float4*)(src + i), dh, dl, i);
}

// ---------------------------------------------------------------------------
// GEMM wrappers (M-tile 256, N-tile 128)
// ---------------------------------------------------------------------------
__global__ __launch_bounds__(256) void k_proj_qk() {
    const int z = blockIdx.z;
    const __nv_bfloat16* bh = z ? g_wkhi : g_wqhi;
    const __nv_bfloat16* bl = z ? g_wklo : g_wqlo;
    __nv_bfloat16* ch = z ? g_Khi : g_Qhi;
    __nv_bfloat16* cl = z ? g_Klo : g_Qlo;
    gemm256_nt(g_xhi, g_xlo, bh, bl, DIMQ, DIMQ, DIMQ / 64,
               blockIdx.y * 256, blockIdx.x * 128, DIMQ,
               nullptr, ch, cl, 1.f, 1);
}

__global__ __launch_bounds__(256) void k_proj_vt() {
    const int b = blockIdx.z;
    gemm256_nt(g_wvhi, g_wvlo,
               g_xhi + (size_t)b * SEQB * DIMQ, g_xlo + (size_t)b * SEQB * DIMQ,
               DIMQ, DIMQ, DIMQ / 64,
               blockIdx.y * 256, blockIdx.x * 128, SEQB,
               nullptr, g_Vthi + (size_t)b * DIMQ * SEQB, g_Vtlo + (size_t)b * DIMQ * SEQB,
               1.f, 1);
}

// Scores: M-tile covers rows [bm*256, bm*256+256). Tile needed iff bn <= 2*bm+1.
// The strictly-upper part inside a kept tile is junk but never read by softmax.
__global__ __launch_bounds__(256) void k_scores() {
    const int bn = blockIdx.x, bm = blockIdx.y, b = blockIdx.z;
    if (bn > 2 * bm + 1) return;
    gemm256_nt(g_Qhi + (size_t)b * SEQB * DIMQ, g_Qlo + (size_t)b * SEQB * DIMQ,
               g_Khi + (size_t)b * SEQB * DIMQ, g_Klo + (size_t)b * SEQB * DIMQ,
               DIMQ, DIMQ, DIMQ / 64, bm * 256, bn * 128, SEQB,
               g_S + (size_t)b * SEQB * SEQB, nullptr, nullptr, 0.03125f, 0);
}

// Out: M-tile 256, K truncated at (bm+1)*256 (P zero-padded to 256 boundary).
__global__ __launch_bounds__(256) void k_out(float* __restrict__ out) {
    const int bn = blockIdx.x, bm = blockIdx.y, b = blockIdx.z;
    gemm256_nt(g_Phi + (size_t)b * SEQB * SEQB, g_Plo + (size_t)b * SEQB * SEQB,
               g_Vthi + (size_t)b * DIMQ * SEQB, g_Vtlo + (size_t)b * DIMQ * SEQB,
               SEQB, SEQB, (bm + 1) * 4, bm * 256, bn * 128, DIMQ,
               out + (size_t)b * SEQB * DIMQ, nullptr, nullptr, 1.f, 0);
}

// ---------------------------------------------------------------------------
// Causal softmax: S fp32 row -> P split hi/lo, zero-padded to 256 boundary
// ---------------------------------------------------------------------------
__global__ __launch_bounds__(256) void k_softmax() {
    const int i = blockIdx.x, b = blockIdx.y;
    const float* row = g_S + ((size_t)b * SEQB + i) * SEQB;
    __nv_bfloat16* ph = g_Phi + ((size_t)b * SEQB + i) * SEQB;
    __nv_bfloat16* pl = g_Plo + ((size_t)b * SEQB + i) * SEQB;
    const int len = i + 1;
    const int t = threadIdx.x;

    float vals[8];
    float m = -1e30f;
#pragma unroll
    for (int k = 0; k < 8; k++) {
        int j = t + k * 256;
        float s = (j < len) ? row[j] : -1e30f;
        vals[k] = s;
        m = fmaxf(m, s);
    }
    __shared__ float red[256];
    red[t] = m;
    __syncthreads();
    for (int s = 128; s > 0; s >>= 1) {
        if (t < s) red[t] = fmaxf(red[t], red[t + s]);
        __syncthreads();
    }
    m = red[0];
    __syncthreads();

    float sum = 0.f;
#pragma unroll
    for (int k = 0; k < 8; k++) {
        int j = t + k * 256;
        if (j < len) { vals[k] = expf(vals[k] - m); sum += vals[k]; }
        else vals[k] = 0.f;
    }
    red[t] = sum;
    __syncthreads();
    for (int s = 128; s > 0; s >>= 1) {
        if (t < s) red[t] += red[t + s];
        __syncthreads();
    }
    const float inv = 1.0f / red[0];

    const int cap = (len + 255) & ~255;   // 256-pad for the 256-tall out tiles
#pragma unroll
    for (int k = 0; k < 8; k++) {
        int j = t + k * 256;
        if (j < cap) {
            float p = vals[k] * inv;
            __nv_bfloat16 h = __float2bfloat16(p);
            __nv_bfloat16 l = __float2bfloat16(p - __bfloat162float(h));
            ph[j] = h;
            pl[j] = l;
        }
    }
}

// ---------------------------------------------------------------------------
extern "C" void kernel_launch(void* const* d_in, const int* in_sizes, int n_in,
                              void* d_out, int out_size)
{
    const float* x  = (const float*)d_in[0];
    const float* Wq = (const float*)d_in[1];
    const float* Wk = (const float*)d_in[2];
    const float* Wv = (const float*)d_in[3];
    float* out = (float*)d_out;

    cudaFuncSetAttribute(k_proj_qk, cudaFuncAttributeMaxDynamicSharedMemorySize, SMEM_SZ);
    cudaFuncSetAttribute(k_proj_vt, cudaFuncAttributeMaxDynamicSharedMemorySize, SMEM_SZ);
    cudaFuncSetAttribute(k_scores,  cudaFuncAttributeMaxDynamicSharedMemorySize, SMEM_SZ);
    cudaFuncSetAttribute(k_out,     cudaFuncAttributeMaxDynamicSharedMemorySize, SMEM_SZ);

    k_conv_x<<<(unsigned)(XE / 1024), 256>>>(x);
    k_conv_w<<<dim3((unsigned)(WE / 1024), 1, 3), 256>>>(Wq, Wk, Wv);

    k_proj_qk<<<dim3(DIMQ / 128, (NB * SEQB) / 256, 2), 256, SMEM_SZ>>>();   // (8,64,2)
    k_proj_vt<<<dim3(SEQB / 128, DIMQ / 256, NB), 256, SMEM_SZ>>>();         // (16,4,8)
    k_scores <<<dim3(SEQB / 128, SEQB / 256, NB), 256, SMEM_SZ>>>();         // (16,8,8)
    k_softmax<<<dim3(SEQB, NB), 256>>>();                                    // (2048,8)
    k_out    <<<dim3(DIMQ / 128, SEQB / 256, NB), 256, SMEM_SZ>>>(out);      // (8,8,8)
}

// round 11
// speedup vs baseline: 1.1654x; 1.1654x over previous
#include <cuda_runtime.h>
#include <cuda_bf16.h>
#include <stdint.h>
#include <math.h>

// Fixed problem dims
#define NB   8
#define SEQB 2048
#define DIMQ 1024

static constexpr size_t XE = (size_t)NB * SEQB * DIMQ;   // 16,777,216
static constexpr size_t WE = (size_t)DIMQ * DIMQ;        // 1,048,576
static constexpr size_t SE = (size_t)NB * SEQB * SEQB;   // 33,554,432

// Scratch (__device__ globals: allocation-free rule)
__device__ __nv_bfloat16 g_xhi[XE],  g_xlo[XE];
__device__ __nv_bfloat16 g_wqhi[WE], g_wqlo[WE];
__device__ __nv_bfloat16 g_wkhi[WE], g_wklo[WE];
__device__ __nv_bfloat16 g_wvhi[WE], g_wvlo[WE];
__device__ __nv_bfloat16 g_Qhi[XE],  g_Qlo[XE];
__device__ __nv_bfloat16 g_Khi[XE],  g_Klo[XE];
__device__ __nv_bfloat16 g_Vthi[XE], g_Vtlo[XE];
__device__ float         g_S[SE];
__device__ __nv_bfloat16 g_Phi[SE],  g_Plo[SE];

// ---------------------------------------------------------------------------
// PTX helpers (baseline PTX only — no 'a'-gated features)
// ---------------------------------------------------------------------------
__device__ __forceinline__ uint32_t smem_u32(const void* p) {
    uint32_t a;
    asm("{ .reg .u64 t; cvta.to.shared.u64 t, %1; cvt.u32.u64 %0, t; }"
        : "=r"(a) : "l"(p));
    return a;
}

__device__ __forceinline__ void ldsm_x4(uint32_t addr, uint32_t& r0, uint32_t& r1,
                                        uint32_t& r2, uint32_t& r3) {
    asm volatile("ldmatrix.sync.aligned.m8n8.x4.shared.b16 {%0,%1,%2,%3}, [%4];"
                 : "=r"(r0), "=r"(r1), "=r"(r2), "=r"(r3) : "r"(addr));
}

__device__ __forceinline__ void mma16816(float& d0, float& d1, float& d2, float& d3,
                                         uint32_t a0, uint32_t a1, uint32_t a2, uint32_t a3,
                                         uint32_t b0, uint32_t b1) {
    asm volatile(
        "mma.sync.aligned.m16n8k16.row.col.f32.bf16.bf16.f32 "
        "{%0,%1,%2,%3}, {%4,%5,%6,%7}, {%8,%9}, {%0,%1,%2,%3};"
        : "+f"(d0), "+f"(d1), "+f"(d2), "+f"(d3)
        : "r"(a0), "r"(a1), "r"(a2), "r"(a3), "r"(b0), "r"(b1));
}

// ---------------------------------------------------------------------------
// GEMM-NT core, fused 3-term split: C[128,128] tile at (m0,n0) =
//   sum_k (Ahi+Alo)[m,k]*(Bhi+Blo)[n,k] dropping the lo*lo term.
// Per K32-chunk, all four tiles (Ahi,Alo,Bhi,Blo) are loaded once and the
// three products accumulate into the same fp32 registers.
// 256 threads = 8 warps (2m x 4n), warp tile 64x32, BK=32, 3-stage cp.async.
// smem/CTA = 96KB -> 2 CTAs/SM (16 warps), regs capped at 128.
// Tiles are 128 rows x 64B with line-XOR swizzle (conflict-free ldmatrix).
// mode 0: write fp32*alpha; mode 1: write split hi/lo bf16.
// ---------------------------------------------------------------------------
#define STAGES  3
#define TILE_B  8192                        // 128 rows x 64 bytes
#define CHUNK_B (4 * TILE_B)                // Ahi,Alo,Bhi,Blo
#define SMEM_SZ (STAGES * CHUNK_B)          // 98304

__device__ __forceinline__ void gemm128_nt(
    const __nv_bfloat16* __restrict__ Ahi, const __nv_bfloat16* __restrict__ Alo,
    const __nv_bfloat16* __restrict__ Bhi, const __nv_bfloat16* __restrict__ Blo,
    int lda, int ldb, int kb32, int m0, int n0, int ldc,
    float* __restrict__ C32,
    __nv_bfloat16* __restrict__ Chi, __nv_bfloat16* __restrict__ Clo,
    float alpha, int mode)
{
    extern __shared__ char smem[];
    const uint32_t sbase = smem_u32(smem);
    const int tid  = threadIdx.x;
    const int wid  = tid >> 5;
    const int lane = tid & 31;
    const int wm = wid >> 2;      // 0..1 (64-row slab)
    const int wn = wid & 3;       // 0..3 (32-col slab)

    auto load_chunk = [&](int c, int s) {
        const int k0 = c * 32;
        const uint32_t st = sbase + s * CHUNK_B;
#pragma unroll
        for (int i = 0; i < 2; i++) {
            int o = tid + i * 256;            // 0..511 : 128 rows x 4 x 16B
            int row = o >> 2, seg = o & 3;
            uint32_t off = (uint32_t)(row * 64 + seg * 16);
            uint32_t sw = off ^ ((((uint32_t)row >> 1) & 3u) << 4);
            size_t ao = (size_t)(m0 + row) * lda + k0 + seg * 8;
            size_t bo = (size_t)(n0 + row) * ldb + k0 + seg * 8;
            asm volatile("cp.async.cg.shared.global [%0], [%1], 16;" :: "r"(st + sw),              "l"(Ahi + ao));
            asm volatile("cp.async.cg.shared.global [%0], [%1], 16;" :: "r"(st + TILE_B + sw),     "l"(Alo + ao));
            asm volatile("cp.async.cg.shared.global [%0], [%1], 16;" :: "r"(st + 2 * TILE_B + sw), "l"(Bhi + bo));
            asm volatile("cp.async.cg.shared.global [%0], [%1], 16;" :: "r"(st + 3 * TILE_B + sw), "l"(Blo + bo));
        }
        asm volatile("cp.async.commit_group;" ::: "memory");
    };

    float acc[4][4][4];
#pragma unroll
    for (int i = 0; i < 4; i++)
#pragma unroll
        for (int j = 0; j < 4; j++)
#pragma unroll
            for (int k = 0; k < 4; k++) acc[i][j][k] = 0.f;

    // Prologue: 2 chunks in flight (kb32 >= 4 in all call sites)
    load_chunk(0, 0);
    load_chunk(1, 1);

    const int lrow = lane & 15;
    const int lhi  = (lane >> 4) & 1;

    for (int c = 0; c < kb32; c++) {
        const int s = c % STAGES;
        asm volatile("cp.async.wait_group 1;" ::: "memory");   // chunk c resident
        __syncthreads();

        const int nxt = c + 2;
        if (nxt < kb32) load_chunk(nxt, nxt % STAGES);
        else asm volatile("cp.async.commit_group;" ::: "memory");  // uniform counts

        const uint32_t st = sbase + s * CHUNK_B;
#pragma unroll
        for (int kk = 0; kk < 2; kk++) {
            const uint32_t c16 = (uint32_t)(kk * 2 + lhi);   // 16B column index
            uint32_t a[4][4], b[2][4], bl[2][4];
#pragma unroll
            for (int mf = 0; mf < 4; mf++) {
                int row = wm * 64 + mf * 16 + lrow;
                uint32_t sw = (uint32_t)(row * 64) + ((c16 ^ (((uint32_t)row >> 1) & 3u)) << 4);
                ldsm_x4(st + sw, a[mf][0], a[mf][1], a[mf][2], a[mf][3]);
            }
#pragma unroll
            for (int nf2 = 0; nf2 < 2; nf2++) {
                int row = wn * 32 + nf2 * 16 + lrow;
                uint32_t sw = (uint32_t)(row * 64) + ((c16 ^ (((uint32_t)row >> 1) & 3u)) << 4);
                ldsm_x4(st + 2 * TILE_B + sw, b[nf2][0], b[nf2][1], b[nf2][2], b[nf2][3]);
                ldsm_x4(st + 3 * TILE_B + sw, bl[nf2][0], bl[nf2][1], bl[nf2][2], bl[nf2][3]);
            }
            // hi*hi and hi*lo (Ahi fragments still live)
#pragma unroll
            for (int mf = 0; mf < 4; mf++)
#pragma unroll
                for (int nf = 0; nf < 4; nf++) {
                    uint32_t h0 = (nf & 1) ? b[nf >> 1][1] : b[nf >> 1][0];
                    uint32_t h1 = (nf & 1) ? b[nf >> 1][3] : b[nf >> 1][2];
                    mma16816(acc[mf][nf][0], acc[mf][nf][1], acc[mf][nf][2], acc[mf][nf][3],
                             a[mf][0], a[mf][1], a[mf][2], a[mf][3], h0, h1);
                    uint32_t l0 = (nf & 1) ? bl[nf >> 1][1] : bl[nf >> 1][0];
                    uint32_t l1 = (nf & 1) ? bl[nf >> 1][3] : bl[nf >> 1][2];
                    mma16816(acc[mf][nf][0], acc[mf][nf][1], acc[mf][nf][2], acc[mf][nf][3],
                             a[mf][0], a[mf][1], a[mf][2], a[mf][3], l0, l1);
                }
            // lo*hi (Ahi dead; reuse register space for Alo)
#pragma unroll
            for (int mf = 0; mf < 4; mf++) {
                int row = wm * 64 + mf * 16 + lrow;
                uint32_t sw = (uint32_t)(row * 64) + ((c16 ^ (((uint32_t)row >> 1) & 3u)) << 4);
                ldsm_x4(st + TILE_B + sw, a[mf][0], a[mf][1], a[mf][2], a[mf][3]);
            }
#pragma unroll
            for (int mf = 0; mf < 4; mf++)
#pragma unroll
                for (int nf = 0; nf < 4; nf++) {
                    uint32_t h0 = (nf & 1) ? b[nf >> 1][1] : b[nf >> 1][0];
                    uint32_t h1 = (nf & 1) ? b[nf >> 1][3] : b[nf >> 1][2];
                    mma16816(acc[mf][nf][0], acc[mf][nf][1], acc[mf][nf][2], acc[mf][nf][3],
                             a[mf][0], a[mf][1], a[mf][2], a[mf][3], h0, h1);
                }
        }
    }

    // Epilogue: straight from registers.
#pragma unroll
    for (int mf = 0; mf < 4; mf++) {
#pragma unroll
        for (int nf = 0; nf < 4; nf++) {
            const int r0  = m0 + wm * 64 + mf * 16 + (lane >> 2);
            const int col = n0 + wn * 32 + nf * 8 + (lane & 3) * 2;
            float d0 = acc[mf][nf][0], d1 = acc[mf][nf][1];
            float d2 = acc[mf][nf][2], d3 = acc[mf][nf][3];
            if (mode == 0) {
                float2 u, v;
                u.x = d0 * alpha; u.y = d1 * alpha;
                v.x = d2 * alpha; v.y = d3 * alpha;
                *(float2*)(C32 + (size_t)r0 * ldc + col)       = u;
                *(float2*)(C32 + (size_t)(r0 + 8) * ldc + col) = v;
            } else {
                float f[4] = {d0, d1, d2, d3};
                unsigned short hs[4], ls[4];
#pragma unroll
                for (int k = 0; k < 4; k++) {
                    __nv_bfloat16 h = __float2bfloat16(f[k]);
                    __nv_bfloat16 l = __float2bfloat16(f[k] - __bfloat162float(h));
                    hs[k] = __bfloat16_as_ushort(h);
                    ls[k] = __bfloat16_as_ushort(l);
                }
                *(uint32_t*)(Chi + (size_t)r0 * ldc + col)       = hs[0] | ((uint32_t)hs[1] << 16);
                *(uint32_t*)(Chi + (size_t)(r0 + 8) * ldc + col) = hs[2] | ((uint32_t)hs[3] << 16);
                *(uint32_t*)(Clo + (size_t)r0 * ldc + col)       = ls[0] | ((uint32_t)ls[1] << 16);
                *(uint32_t*)(Clo + (size_t)(r0 + 8) * ldc + col) = ls[2] | ((uint32_t)ls[3] << 16);
            }
        }
    }
}

// ---------------------------------------------------------------------------
// Conversion kernels: fp32 -> bf16 hi/lo split
// ---------------------------------------------------------------------------
__device__ __forceinline__ void split4_store(float4 v, __nv_bfloat16* dh, __nv_bfloat16* dl, size_t i) {
    float f[4] = {v.x, v.y, v.z, v.w};
    unsigned short hs[4], ls[4];
#pragma unroll
    for (int k = 0; k < 4; k++) {
        __nv_bfloat16 h = __float2bfloat16(f[k]);
        __nv_bfloat16 l = __float2bfloat16(f[k] - __bfloat162float(h));
        hs[k] = __bfloat16_as_ushort(h);
        ls[k] = __bfloat16_as_ushort(l);
    }
    *(uint2*)(dh + i) = make_uint2(hs[0] | ((uint32_t)hs[1] << 16), hs[2] | ((uint32_t)hs[3] << 16));
    *(uint2*)(dl + i) = make_uint2(ls[0] | ((uint32_t)ls[1] << 16), ls[2] | ((uint32_t)ls[3] << 16));
}

__global__ __launch_bounds__(256) void k_conv_x(const float* __restrict__ x) {
    size_t i = ((size_t)blockIdx.x * 256 + threadIdx.x) * 4;
    split4_store(*(const float4*)(x + i), g_xhi, g_xlo, i);
}

__global__ __launch_bounds__(256) void k_conv_w(const float* __restrict__ Wq,
                                                const float* __restrict__ Wk,
                                                const float* __restrict__ Wv) {
    const int z = blockIdx.z;
    const float* src = (z == 0) ? Wq : (z == 1) ? Wk : Wv;
    __nv_bfloat16* dh = (z == 0) ? g_wqhi : (z == 1) ? g_wkhi : g_wvhi;
    __nv_bfloat16* dl = (z == 0) ? g_wqlo : (z == 1) ? g_wklo : g_wvlo;
    size_t i = ((size_t)blockIdx.x * 256 + threadIdx.x) * 4;
    split4_store(*(const float4*)(src + i), dh, dl, i);
}

// ---------------------------------------------------------------------------
// GEMM wrappers (CTA tile 128x128)
// ---------------------------------------------------------------------------
__global__ __launch_bounds__(256, 2) void k_proj_qk() {
    const int z = blockIdx.z;
    const __nv_bfloat16* bh = z ? g_wkhi : g_wqhi;
    const __nv_bfloat16* bl = z ? g_wklo : g_wqlo;
    __nv_bfloat16* ch = z ? g_Khi : g_Qhi;
    __nv_bfloat16* cl = z ? g_Klo : g_Qlo;
    gemm128_nt(g_xhi, g_xlo, bh, bl, DIMQ, DIMQ, DIMQ / 32,
               blockIdx.y * 128, blockIdx.x * 128, DIMQ,
               nullptr, ch, cl, 1.f, 1);
}

__global__ __launch_bounds__(256, 2) void k_proj_vt() {
    const int b = blockIdx.z;
    gemm128_nt(g_wvhi, g_wvlo,
               g_xhi + (size_t)b * SEQB * DIMQ, g_xlo + (size_t)b * SEQB * DIMQ,
               DIMQ, DIMQ, DIMQ / 32,
               blockIdx.y * 128, blockIdx.x * 128, SEQB,
               nullptr, g_Vthi + (size_t)b * DIMQ * SEQB, g_Vtlo + (size_t)b * DIMQ * SEQB,
               1.f, 1);
}

__global__ __launch_bounds__(256, 2) void k_scores() {
    const int bn = blockIdx.x, bm = blockIdx.y, b = blockIdx.z;
    if (bn > bm) return;
    gemm128_nt(g_Qhi + (size_t)b * SEQB * DIMQ, g_Qlo + (size_t)b * SEQB * DIMQ,
               g_Khi + (size_t)b * SEQB * DIMQ, g_Klo + (size_t)b * SEQB * DIMQ,
               DIMQ, DIMQ, DIMQ / 32, bm * 128, bn * 128, SEQB,
               g_S + (size_t)b * SEQB * SEQB, nullptr, nullptr, 0.03125f, 0);
}

__global__ __launch_bounds__(256, 2) void k_out(float* __restrict__ out) {
    const int bn = blockIdx.x, bm = blockIdx.y, b = blockIdx.z;
    gemm128_nt(g_Phi + (size_t)b * SEQB * SEQB, g_Plo + (size_t)b * SEQB * SEQB,
               g_Vthi + (size_t)b * DIMQ * SEQB, g_Vtlo + (size_t)b * DIMQ * SEQB,
               SEQB, SEQB, (bm + 1) * 4, bm * 128, bn * 128, DIMQ,
               out + (size_t)b * SEQB * DIMQ, nullptr, nullptr, 1.f, 0);
}

// ---------------------------------------------------------------------------
// Causal softmax: S fp32 row -> P split hi/lo, zero-padded to 128 boundary
// ---------------------------------------------------------------------------
__global__ __launch_bounds__(256) void k_softmax() {
    const int i = blockIdx.x, b = blockIdx.y;
    const float* row = g_S + ((size_t)b * SEQB + i) * SEQB;
    __nv_bfloat16* ph = g_Phi + ((size_t)b * SEQB + i) * SEQB;
    __nv_bfloat16* pl = g_Plo + ((size_t)b * SEQB + i) * SEQB;
    const int len = i + 1;
    const int t = threadIdx.x;

    float vals[8];
    float m = -1e30f;
#pragma unroll
    for (int k = 0; k < 8; k++) {
        int j = t + k * 256;
        float s = (j < len) ? row[j] : -1e30f;
        vals[k] = s;
        m = fmaxf(m, s);
    }
    __shared__ float red[256];
    red[t] = m;
    __syncthreads();
    for (int s = 128; s > 0; s >>= 1) {
        if (t < s) red[t] = fmaxf(red[t], red[t + s]);
        __syncthreads();
    }
    m = red[0];
    __syncthreads();

    float sum = 0.f;
#pragma unroll
    for (int k = 0; k < 8; k++) {
        int j = t + k * 256;
        if (j < len) { vals[k] = expf(vals[k] - m); sum += vals[k]; }
        else vals[k] = 0.f;
    }
    red[t] = sum;
    __syncthreads();
    for (int s = 128; s > 0; s >>= 1) {
        if (t < s) red[t] += red[t + s];
        __syncthreads();
    }
    const float inv = 1.0f / red[0];

    const int cap = (len + 127) & ~127;
#pragma unroll
    for (int k = 0; k < 8; k++) {
        int j = t + k * 256;
        if (j < cap) {
            float p = vals[k] * inv;
            __nv_bfloat16 h = __float2bfloat16(p);
            __nv_bfloat16 l = __float2bfloat16(p - __bfloat162float(h));
            ph[j] = h;
            pl[j] = l;
        }
    }
}

// ---------------------------------------------------------------------------
extern "C" void kernel_launch(void* const* d_in, const int* in_sizes, int n_in,
                              void* d_out, int out_size)
{
    const float* x  = (const float*)d_in[0];
    const float* Wq = (const float*)d_in[1];
    const float* Wk = (const float*)d_in[2];
    const float* Wv = (const float*)d_in[3];
    float* out = (float*)d_out;

    cudaFuncSetAttribute(k_proj_qk, cudaFuncAttributeMaxDynamicSharedMemorySize, SMEM_SZ);
    cudaFuncSetAttribute(k_proj_vt, cudaFuncAttributeMaxDynamicSharedMemorySize, SMEM_SZ);
    cudaFuncSetAttribute(k_scores,  cudaFuncAttributeMaxDynamicSharedMemorySize, SMEM_SZ);
    cudaFuncSetAttribute(k_out,     cudaFuncAttributeMaxDynamicSharedMemorySize, SMEM_SZ);

    k_conv_x<<<(unsigned)(XE / 1024), 256>>>(x);
    k_conv_w<<<dim3((unsigned)(WE / 1024), 1, 3), 256>>>(Wq, Wk, Wv);

    k_proj_qk<<<dim3(DIMQ / 128, (NB * SEQB) / 128, 2), 256, SMEM_SZ>>>();   // (8,128,2)
    k_proj_vt<<<dim3(SEQB / 128, DIMQ / 128, NB), 256, SMEM_SZ>>>();         // (16,8,8)
    k_scores <<<dim3(SEQB / 128, SEQB / 128, NB), 256, SMEM_SZ>>>();         // (16,16,8)
    k_softmax<<<dim3(SEQB, NB), 256>>>();                                    // (2048,8)
    k_out    <<<dim3(DIMQ / 128, SEQB / 128, NB), 256, SMEM_SZ>>>(out);      // (8,16,8)
}

// round 12
// speedup vs baseline: 1.6311x; 1.3996x over previous
#include <cuda_runtime.h>
#include <cuda_fp16.h>
#include <stdint.h>
#include <math.h>

// Fixed problem dims
#define NB   8
#define SEQB 2048
#define DIMQ 1024

static constexpr size_t XE = (size_t)NB * SEQB * DIMQ;   // 16,777,216
static constexpr size_t WE = (size_t)DIMQ * DIMQ;        // 1,048,576
static constexpr size_t SE = (size_t)NB * SEQB * SEQB;   // 33,554,432

// Scratch (__device__ globals: allocation-free rule)
__device__ __half g_xhi[XE],  g_xlo[XE];
__device__ __half g_wqhi[WE];                    // hi only (B operand)
__device__ __half g_wkhi[WE];                    // hi only
__device__ __half g_wvhi[WE], g_wvlo[WE];        // split (A operand in proj_vt)
__device__ __half g_Qhi[XE],  g_Qlo[XE];         // split (A in scores)
__device__ __half g_Khi[XE];                     // hi only (B in scores)
__device__ __half g_Vthi[XE];                    // hi only (B in out)
__device__ float  g_S[SE];
__device__ __half g_Phi[SE],  g_Plo[SE];         // split (A in out)

// ---------------------------------------------------------------------------
// PTX helpers (baseline PTX only — no 'a'-gated features)
// ---------------------------------------------------------------------------
__device__ __forceinline__ uint32_t smem_u32(const void* p) {
    uint32_t a;
    asm("{ .reg .u64 t; cvta.to.shared.u64 t, %1; cvt.u32.u64 %0, t; }"
        : "=r"(a) : "l"(p));
    return a;
}

__device__ __forceinline__ void ldsm_x4(uint32_t addr, uint32_t& r0, uint32_t& r1,
                                        uint32_t& r2, uint32_t& r3) {
    asm volatile("ldmatrix.sync.aligned.m8n8.x4.shared.b16 {%0,%1,%2,%3}, [%4];"
                 : "=r"(r0), "=r"(r1), "=r"(r2), "=r"(r3) : "r"(addr));
}

__device__ __forceinline__ void mma16816(float& d0, float& d1, float& d2, float& d3,
                                         uint32_t a0, uint32_t a1, uint32_t a2, uint32_t a3,
                                         uint32_t b0, uint32_t b1) {
    asm volatile(
        "mma.sync.aligned.m16n8k16.row.col.f32.f16.f16.f32 "
        "{%0,%1,%2,%3}, {%4,%5,%6,%7}, {%8,%9}, {%0,%1,%2,%3};"
        : "+f"(d0), "+f"(d1), "+f"(d2), "+f"(d3)
        : "r"(a0), "r"(a1), "r"(a2), "r"(a3), "r"(b0), "r"(b1));
}

// ---------------------------------------------------------------------------
// GEMM-NT core, fp16 2-term: C[128,128] tile at (m0,n0) =
//   sum_k (Ahi+Alo)[m,k] * Bhi[n,k]       (fp32 accumulate)
// A exact (fp16 hi/lo split), B fp16-rounded: error ~2.8e-4 rel per GEMM.
// 256 threads = 8 warps (2m x 4n), warp tile 64x32, BK=32, 4-stage cp.async,
// prefetch depth 3. smem/CTA = 96KB -> 2 CTAs/SM, regs <= 128.
// Tiles 128 rows x 64B, row-pair XOR swizzle (conflict-free ldmatrix).
// mode 0: fp32*alpha; mode 1: split hi/lo fp16; mode 2: hi-only fp16.
// ---------------------------------------------------------------------------
#define STAGES  4
#define TILE_B  8192                        // 128 rows x 64 bytes
#define CHUNK_B (3 * TILE_B)                // Ahi, Alo, Bhi
#define SMEM_SZ (STAGES * CHUNK_B)          // 98304

__device__ __forceinline__ void gemm128_nt(
    const __half* __restrict__ Ahi, const __half* __restrict__ Alo,
    const __half* __restrict__ Bhi,
    int lda, int ldb, int kb32, int m0, int n0, int ldc,
    float* __restrict__ C32,
    __half* __restrict__ Chi, __half* __restrict__ Clo,
    float alpha, int mode)
{
    extern __shared__ char smem[];
    const uint32_t sbase = smem_u32(smem);
    const int tid  = threadIdx.x;
    const int wid  = tid >> 5;
    const int lane = tid & 31;
    const int wm = wid >> 2;      // 0..1 (64-row slab)
    const int wn = wid & 3;       // 0..3 (32-col slab)

    auto load_chunk = [&](int c, int s) {
        const int k0 = c * 32;
        const uint32_t st = sbase + s * CHUNK_B;
#pragma unroll
        for (int i = 0; i < 2; i++) {
            int o = tid + i * 256;            // 0..511 : 128 rows x 4 x 16B
            int row = o >> 2, seg = o & 3;
            uint32_t off = (uint32_t)(row * 64 + seg * 16);
            uint32_t sw = off ^ ((((uint32_t)row >> 1) & 3u) << 4);
            size_t ao = (size_t)(m0 + row) * lda + k0 + seg * 8;
            size_t bo = (size_t)(n0 + row) * ldb + k0 + seg * 8;
            asm volatile("cp.async.cg.shared.global [%0], [%1], 16;" :: "r"(st + sw),              "l"(Ahi + ao));
            asm volatile("cp.async.cg.shared.global [%0], [%1], 16;" :: "r"(st + TILE_B + sw),     "l"(Alo + ao));
            asm volatile("cp.async.cg.shared.global [%0], [%1], 16;" :: "r"(st + 2 * TILE_B + sw), "l"(Bhi + bo));
        }
        asm volatile("cp.async.commit_group;" ::: "memory");
    };

    float acc[4][4][4];
#pragma unroll
    for (int i = 0; i < 4; i++)
#pragma unroll
        for (int j = 0; j < 4; j++)
#pragma unroll
            for (int k = 0; k < 4; k++) acc[i][j][k] = 0.f;

    // Prologue: 3 chunks in flight (kb32 >= 4 at all call sites)
    load_chunk(0, 0);
    load_chunk(1, 1);
    load_chunk(2, 2);

    const int lrow = lane & 15;
    const int lhi  = (lane >> 4) & 1;

    for (int c = 0; c < kb32; c++) {
        const int s = c % STAGES;
        asm volatile("cp.async.wait_group 2;" ::: "memory");   // chunk c resident
        __syncthreads();

        const int nxt = c + 3;
        if (nxt < kb32) load_chunk(nxt, nxt % STAGES);
        else asm volatile("cp.async.commit_group;" ::: "memory");  // uniform counts

        const uint32_t st = sbase + s * CHUNK_B;
#pragma unroll
        for (int kk = 0; kk < 2; kk++) {
            const uint32_t c16 = (uint32_t)(kk * 2 + lhi);   // 16B column index
            uint32_t a[4][4], al[4][4], b[2][4];
#pragma unroll
            for (int mf = 0; mf < 4; mf++) {
                int row = wm * 64 + mf * 16 + lrow;
                uint32_t sw = (uint32_t)(row * 64) + ((c16 ^ (((uint32_t)row >> 1) & 3u)) << 4);
                ldsm_x4(st + sw, a[mf][0], a[mf][1], a[mf][2], a[mf][3]);
                ldsm_x4(st + TILE_B + sw, al[mf][0], al[mf][1], al[mf][2], al[mf][3]);
            }
#pragma unroll
            for (int nf2 = 0; nf2 < 2; nf2++) {
                int row = wn * 32 + nf2 * 16 + lrow;
                uint32_t sw = (uint32_t)(row * 64) + ((c16 ^ (((uint32_t)row >> 1) & 3u)) << 4);
                ldsm_x4(st + 2 * TILE_B + sw, b[nf2][0], b[nf2][1], b[nf2][2], b[nf2][3]);
            }
#pragma unroll
            for (int mf = 0; mf < 4; mf++)
#pragma unroll
                for (int nf = 0; nf < 4; nf++) {
                    uint32_t h0 = (nf & 1) ? b[nf >> 1][1] : b[nf >> 1][0];
                    uint32_t h1 = (nf & 1) ? b[nf >> 1][3] : b[nf >> 1][2];
                    mma16816(acc[mf][nf][0], acc[mf][nf][1], acc[mf][nf][2], acc[mf][nf][3],
                             a[mf][0], a[mf][1], a[mf][2], a[mf][3], h0, h1);
                    mma16816(acc[mf][nf][0], acc[mf][nf][1], acc[mf][nf][2], acc[mf][nf][3],
                             al[mf][0], al[mf][1], al[mf][2], al[mf][3], h0, h1);
                }
        }
    }

    // Epilogue: straight from registers.
#pragma unroll
    for (int mf = 0; mf < 4; mf++) {
#pragma unroll
        for (int nf = 0; nf < 4; nf++) {
            const int r0  = m0 + wm * 64 + mf * 16 + (lane >> 2);
            const int col = n0 + wn * 32 + nf * 8 + (lane & 3) * 2;
            float d0 = acc[mf][nf][0], d1 = acc[mf][nf][1];
            float d2 = acc[mf][nf][2], d3 = acc[mf][nf][3];
            if (mode == 0) {
                float2 u, v;
                u.x = d0 * alpha; u.y = d1 * alpha;
                v.x = d2 * alpha; v.y = d3 * alpha;
                *(float2*)(C32 + (size_t)r0 * ldc + col)       = u;
                *(float2*)(C32 + (size_t)(r0 + 8) * ldc + col) = v;
            } else if (mode == 1) {
                float f[4] = {d0, d1, d2, d3};
                unsigned short hs[4], ls[4];
#pragma unroll
                for (int k = 0; k < 4; k++) {
                    __half h = __float2half_rn(f[k]);
                    __half l = __float2half_rn(f[k] - __half2float(h));
                    hs[k] = __half_as_ushort(h);
                    ls[k] = __half_as_ushort(l);
                }
                *(uint32_t*)(Chi + (size_t)r0 * ldc + col)       = hs[0] | ((uint32_t)hs[1] << 16);
                *(uint32_t*)(Chi + (size_t)(r0 + 8) * ldc + col) = hs[2] | ((uint32_t)hs[3] << 16);
                *(uint32_t*)(Clo + (size_t)r0 * ldc + col)       = ls[0] | ((uint32_t)ls[1] << 16);
                *(uint32_t*)(Clo + (size_t)(r0 + 8) * ldc + col) = ls[2] | ((uint32_t)ls[3] << 16);
            } else {  // mode 2: hi only
                unsigned short h0 = __half_as_ushort(__float2half_rn(d0));
                unsigned short h1 = __half_as_ushort(__float2half_rn(d1));
                unsigned short h2 = __half_as_ushort(__float2half_rn(d2));
                unsigned short h3 = __half_as_ushort(__float2half_rn(d3));
                *(uint32_t*)(Chi + (size_t)r0 * ldc + col)       = h0 | ((uint32_t)h1 << 16);
                *(uint32_t*)(Chi + (size_t)(r0 + 8) * ldc + col) = h2 | ((uint32_t)h3 << 16);
            }
        }
    }
}

// ---------------------------------------------------------------------------
// Conversion kernels: fp32 -> fp16 hi/lo split (or hi only)
// ---------------------------------------------------------------------------
__device__ __forceinline__ void split4_store(float4 v, __half* dh, __half* dl, size_t i) {
    float f[4] = {v.x, v.y, v.z, v.w};
    unsigned short hs[4], ls[4];
#pragma unroll
    for (int k = 0; k < 4; k++) {
        __half h = __float2half_rn(f[k]);
        __half l = __float2half_rn(f[k] - __half2float(h));
        hs[k] = __half_as_ushort(h);
        ls[k] = __half_as_ushort(l);
    }
    *(uint2*)(dh + i) = make_uint2(hs[0] | ((uint32_t)hs[1] << 16), hs[2] | ((uint32_t)hs[3] << 16));
    *(uint2*)(dl + i) = make_uint2(ls[0] | ((uint32_t)ls[1] << 16), ls[2] | ((uint32_t)ls[3] << 16));
}

__device__ __forceinline__ void hi4_store(float4 v, __half* dh, size_t i) {
    unsigned short h0 = __half_as_ushort(__float2half_rn(v.x));
    unsigned short h1 = __half_as_ushort(__float2half_rn(v.y));
    unsigned short h2 = __half_as_ushort(__float2half_rn(v.z));
    unsigned short h3 = __half_as_ushort(__float2half_rn(v.w));
    *(uint2*)(dh + i) = make_uint2(h0 | ((uint32_t)h1 << 16), h2 | ((uint32_t)h3 << 16));
}

__global__ __launch_bounds__(256) void k_conv_x(const float* __restrict__ x) {
    size_t i = ((size_t)blockIdx.x * 256 + threadIdx.x) * 4;
    split4_store(*(const float4*)(x + i), g_xhi, g_xlo, i);
}

__global__ __launch_bounds__(256) void k_conv_w(const float* __restrict__ Wq,
                                                const float* __restrict__ Wk,
                                                const float* __restrict__ Wv) {
    const int z = blockIdx.z;
    size_t i = ((size_t)blockIdx.x * 256 + threadIdx.x) * 4;
    if (z == 0)      hi4_store(*(const float4*)(Wq + i), g_wqhi, i);
    else if (z == 1) hi4_store(*(const float4*)(Wk + i), g_wkhi, i);
    else             split4_store(*(const float4*)(Wv + i), g_wvhi, g_wvlo, i);
}

// ---------------------------------------------------------------------------
// GEMM wrappers (CTA tile 128x128)
// ---------------------------------------------------------------------------
// Q/K projection: A = x (split), B = W hi. Q stored split; K stored hi-only.
__global__ __launch_bounds__(256, 2) void k_proj_qk() {
    const int z = blockIdx.z;
    gemm128_nt(g_xhi, g_xlo, z ? g_wkhi : g_wqhi,
               DIMQ, DIMQ, DIMQ / 32,
               blockIdx.y * 128, blockIdx.x * 128, DIMQ,
               nullptr,
               z ? g_Khi : g_Qhi, z ? nullptr : g_Qlo,
               1.f, z ? 2 : 1);
}

// Vt projection: A = Wv (split), B = x_b hi. Vt stored hi-only.
__global__ __launch_bounds__(256, 2) void k_proj_vt() {
    const int b = blockIdx.z;
    gemm128_nt(g_wvhi, g_wvlo, g_xhi + (size_t)b * SEQB * DIMQ,
               DIMQ, DIMQ, DIMQ / 32,
               blockIdx.y * 128, blockIdx.x * 128, SEQB,
               nullptr, g_Vthi + (size_t)b * DIMQ * SEQB, nullptr, 1.f, 2);
}

// Scores: A = Q (split), B = K hi. Lower-tri blocks only, fp32 out.
__global__ __launch_bounds__(256, 2) void k_scores() {
    const int bn = blockIdx.x, bm = blockIdx.y, b = blockIdx.z;
    if (bn > bm) return;
    gemm128_nt(g_Qhi + (size_t)b * SEQB * DIMQ, g_Qlo + (size_t)b * SEQB * DIMQ,
               g_Khi + (size_t)b * SEQB * DIMQ,
               DIMQ, DIMQ, DIMQ / 32, bm * 128, bn * 128, SEQB,
               g_S + (size_t)b * SEQB * SEQB, nullptr, nullptr, 0.03125f, 0);
}

// Out: A = P (split), B = Vt hi. K truncated at (bm+1)*128.
__global__ __launch_bounds__(256, 2) void k_out(float* __restrict__ out) {
    const int bn = blockIdx.x, bm = blockIdx.y, b = blockIdx.z;
    gemm128_nt(g_Phi + (size_t)b * SEQB * SEQB, g_Plo + (size_t)b * SEQB * SEQB,
               g_Vthi + (size_t)b * DIMQ * SEQB,
               SEQB, SEQB, (bm + 1) * 4, bm * 128, bn * 128, DIMQ,
               out + (size_t)b * SEQB * DIMQ, nullptr, nullptr, 1.f, 0);
}

// ---------------------------------------------------------------------------
// Causal softmax: S fp32 row -> P split hi/lo fp16, zero-padded to 128 boundary
// ---------------------------------------------------------------------------
__global__ __launch_bounds__(256) void k_softmax() {
    const int i = blockIdx.x, b = blockIdx.y;
    const float* row = g_S + ((size_t)b * SEQB + i) * SEQB;
    __half* ph = g_Phi + ((size_t)b * SEQB + i) * SEQB;
    __half* pl = g_Plo + ((size_t)b * SEQB + i) * SEQB;
    const int len = i + 1;
    const int t = threadIdx.x;

    float vals[8];
    float m = -1e30f;
#pragma unroll
    for (int k = 0; k < 8; k++) {
        int j = t + k * 256;
        float s = (j < len) ? row[j] : -1e30f;
        vals[k] = s;
        m = fmaxf(m, s);
    }
    __shared__ float red[256];
    red[t] = m;
    __syncthreads();
    for (int s = 128; s > 0; s >>= 1) {
        if (t < s) red[t] = fmaxf(red[t], red[t + s]);
        __syncthreads();
    }
    m = red[0];
    __syncthreads();

    float sum = 0.f;
#pragma unroll
    for (int k = 0; k < 8; k++) {
        int j = t + k * 256;
        if (j < len) { vals[k] = expf(vals[k] - m); sum += vals[k]; }
        else vals[k] = 0.f;
    }
    red[t] = sum;
    __syncthreads();
    for (int s = 128; s > 0; s >>= 1) {
        if (t < s) red[t] += red[t + s];
        __syncthreads();
    }
    const float inv = 1.0f / red[0];

    const int cap = (len + 127) & ~127;
#pragma unroll
    for (int k = 0; k < 8; k++) {
        int j = t + k * 256;
        if (j < cap) {
            float p = vals[k] * inv;
            __half h = __float2half_rn(p);
            __half l = __float2half_rn(p - __half2float(h));
            ph[j] = h;
            pl[j] = l;
        }
    }
}

// ---------------------------------------------------------------------------
extern "C" void kernel_launch(void* const* d_in, const int* in_sizes, int n_in,
                              void* d_out, int out_size)
{
    const float* x  = (const float*)d_in[0];
    const float* Wq = (const float*)d_in[1];
    const float* Wk = (const float*)d_in[2];
    const float* Wv = (const float*)d_in[3];
    float* out = (float*)d_out;

    cudaFuncSetAttribute(k_proj_qk, cudaFuncAttributeMaxDynamicSharedMemorySize, SMEM_SZ);
    cudaFuncSetAttribute(k_proj_vt, cudaFuncAttributeMaxDynamicSharedMemorySize, SMEM_SZ);
    cudaFuncSetAttribute(k_scores,  cudaFuncAttributeMaxDynamicSharedMemorySize, SMEM_SZ);
    cudaFuncSetAttribute(k_out,     cudaFuncAttributeMaxDynamicSharedMemorySize, SMEM_SZ);

    k_conv_x<<<(unsigned)(XE / 1024), 256>>>(x);
    k_conv_w<<<dim3((unsigned)(WE / 1024), 1, 3), 256>>>(Wq, Wk, Wv);

    k_proj_qk<<<dim3(DIMQ / 128, (NB * SEQB) / 128, 2), 256, SMEM_SZ>>>();   // (8,128,2)
    k_proj_vt<<<dim3(SEQB / 128, DIMQ / 128, NB), 256, SMEM_SZ>>>();         // (16,8,8)
    k_scores <<<dim3(SEQB / 128, SEQB / 128, NB), 256, SMEM_SZ>>>();         // (16,16,8)
    k_softmax<<<dim3(SEQB, NB), 256>>>();                                    // (2048,8)
    k_out    <<<dim3(DIMQ / 128, SEQB / 128, NB), 256, SMEM_SZ>>>(out);      // (8,16,8)
}

// round 13
// speedup vs baseline: 3.0696x; 1.8819x over previous
#include <cuda_runtime.h>
#include <cuda_fp16.h>
#include <stdint.h>
#include <math.h>

// Fixed problem dims
#define NB   8
#define SEQB 2048
#define DIMQ 1024

static constexpr size_t XE = (size_t)NB * SEQB * DIMQ;   // 16,777,216
static constexpr size_t WE = (size_t)DIMQ * DIMQ;        // 1,048,576
static constexpr size_t SE = (size_t)NB * SEQB * SEQB;   // 33,554,432

// Scratch (__device__ globals: allocation-free rule). All fp16 hi-only.
__device__ __half g_x[XE];
__device__ __half g_wq[WE], g_wk[WE], g_wv[WE];
__device__ __half g_Q[XE], g_K[XE], g_Vt[XE];
__device__ float  g_S[SE];
__device__ __half g_P[SE];

// ---------------------------------------------------------------------------
// PTX helpers (baseline PTX only — no 'a'-gated features)
// ---------------------------------------------------------------------------
__device__ __forceinline__ uint32_t smem_u32(const void* p) {
    uint32_t a;
    asm("{ .reg .u64 t; cvta.to.shared.u64 t, %1; cvt.u32.u64 %0, t; }"
        : "=r"(a) : "l"(p));
    return a;
}

__device__ __forceinline__ void ldsm_x4(uint32_t addr, uint32_t& r0, uint32_t& r1,
                                        uint32_t& r2, uint32_t& r3) {
    asm volatile("ldmatrix.sync.aligned.m8n8.x4.shared.b16 {%0,%1,%2,%3}, [%4];"
                 : "=r"(r0), "=r"(r1), "=r"(r2), "=r"(r3) : "r"(addr));
}

__device__ __forceinline__ void mma16816(float& d0, float& d1, float& d2, float& d3,
                                         uint32_t a0, uint32_t a1, uint32_t a2, uint32_t a3,
                                         uint32_t b0, uint32_t b1) {
    asm volatile(
        "mma.sync.aligned.m16n8k16.row.col.f32.f16.f16.f32 "
        "{%0,%1,%2,%3}, {%4,%5,%6,%7}, {%8,%9}, {%0,%1,%2,%3};"
        : "+f"(d0), "+f"(d1), "+f"(d2), "+f"(d3)
        : "r"(a0), "r"(a1), "r"(a2), "r"(a3), "r"(b0), "r"(b1));
}

// ---------------------------------------------------------------------------
// GEMM-NT core, plain fp16: C[128,128] tile at (m0,n0) = sum_k A[m,k]*B[n,k]
// (fp32 accumulate). 256 threads = 8 warps (2m x 4n), warp tile 64x32,
// BK=64 (128B rows, SW128 swizzle), 3-stage cp.async ring, 2 CTAs/SM.
// mode 0: write fp32*alpha; mode 2: write fp16.
// ---------------------------------------------------------------------------
#define STAGES  3
#define TILE_B  16384                       // 128 rows x 128 bytes
#define CHUNK_B (2 * TILE_B)                // A, B
#define SMEM_SZ (STAGES * CHUNK_B)          // 98304

__device__ __forceinline__ void gemm128_nt(
    const __half* __restrict__ A, const __half* __restrict__ B,
    int lda, int ldb, int kb64, int m0, int n0, int ldc,
    float* __restrict__ C32, __half* __restrict__ C16,
    float alpha, int mode)
{
    extern __shared__ char smem[];
    const uint32_t sbase = smem_u32(smem);
    const int tid  = threadIdx.x;
    const int wid  = tid >> 5;
    const int lane = tid & 31;
    const int wm = wid >> 2;      // 0..1 (64-row slab)
    const int wn = wid & 3;       // 0..3 (32-col slab)

    auto load_chunk = [&](int c, int s) {
        const int k0 = c * 64;
        const uint32_t st = sbase + s * CHUNK_B;
#pragma unroll
        for (int i = 0; i < 4; i++) {
            int o = tid + i * 256;            // 0..1023 : 128 rows x 8 x 16B
            int row = o >> 3, seg = o & 7;
            uint32_t off = (uint32_t)(o << 4);
            uint32_t sw = off ^ ((off >> 3) & 0x70);
            const __half* ga = A + (size_t)(m0 + row) * lda + k0 + seg * 8;
            const __half* gb = B + (size_t)(n0 + row) * ldb + k0 + seg * 8;
            asm volatile("cp.async.cg.shared.global [%0], [%1], 16;" :: "r"(st + sw),          "l"(ga));
            asm volatile("cp.async.cg.shared.global [%0], [%1], 16;" :: "r"(st + TILE_B + sw), "l"(gb));
        }
        asm volatile("cp.async.commit_group;" ::: "memory");
    };

    float acc[4][4][4];
#pragma unroll
    for (int i = 0; i < 4; i++)
#pragma unroll
        for (int j = 0; j < 4; j++)
#pragma unroll
            for (int k = 0; k < 4; k++) acc[i][j][k] = 0.f;

    // Prologue: 2 chunks in flight (kb64 >= 2 at all call sites)
    load_chunk(0, 0);
    load_chunk(1, 1);

    const int lrow = lane & 15;
    const int lhi  = (lane >> 4) & 1;

    for (int c = 0; c < kb64; c++) {
        const int s = c % STAGES;
        asm volatile("cp.async.wait_group 1;" ::: "memory");   // chunk c resident
        __syncthreads();

        const int nxt = c + 2;
        if (nxt < kb64) load_chunk(nxt, nxt % STAGES);
        else asm volatile("cp.async.commit_group;" ::: "memory");  // uniform counts

        const uint32_t st = sbase + s * CHUNK_B;
#pragma unroll
        for (int kk = 0; kk < 4; kk++) {
            const uint32_t col = (uint32_t)(kk * 32 + lhi * 16);   // byte column
            uint32_t a[4][4], b[2][4];
#pragma unroll
            for (int mf = 0; mf < 4; mf++) {
                int row = wm * 64 + mf * 16 + lrow;
                uint32_t addr = st + row * 128 + (col ^ ((row & 7) << 4));
                ldsm_x4(addr, a[mf][0], a[mf][1], a[mf][2], a[mf][3]);
            }
#pragma unroll
            for (int nf2 = 0; nf2 < 2; nf2++) {
                int row = wn * 32 + nf2 * 16 + lrow;
                uint32_t addr = st + TILE_B + row * 128 + (col ^ ((row & 7) << 4));
                ldsm_x4(addr, b[nf2][0], b[nf2][1], b[nf2][2], b[nf2][3]);
            }
#pragma unroll
            for (int mf = 0; mf < 4; mf++)
#pragma unroll
                for (int nf = 0; nf < 4; nf++) {
                    uint32_t h0 = (nf & 1) ? b[nf >> 1][1] : b[nf >> 1][0];
                    uint32_t h1 = (nf & 1) ? b[nf >> 1][3] : b[nf >> 1][2];
                    mma16816(acc[mf][nf][0], acc[mf][nf][1], acc[mf][nf][2], acc[mf][nf][3],
                             a[mf][0], a[mf][1], a[mf][2], a[mf][3], h0, h1);
                }
        }
    }

    // Epilogue: straight from registers.
#pragma unroll
    for (int mf = 0; mf < 4; mf++) {
#pragma unroll
        for (int nf = 0; nf < 4; nf++) {
            const int r0  = m0 + wm * 64 + mf * 16 + (lane >> 2);
            const int col = n0 + wn * 32 + nf * 8 + (lane & 3) * 2;
            float d0 = acc[mf][nf][0], d1 = acc[mf][nf][1];
            float d2 = acc[mf][nf][2], d3 = acc[mf][nf][3];
            if (mode == 0) {
                float2 u, v;
                u.x = d0 * alpha; u.y = d1 * alpha;
                v.x = d2 * alpha; v.y = d3 * alpha;
                *(float2*)(C32 + (size_t)r0 * ldc + col)       = u;
                *(float2*)(C32 + (size_t)(r0 + 8) * ldc + col) = v;
            } else {
                unsigned short h0 = __half_as_ushort(__float2half_rn(d0));
                unsigned short h1 = __half_as_ushort(__float2half_rn(d1));
                unsigned short h2 = __half_as_ushort(__float2half_rn(d2));
                unsigned short h3 = __half_as_ushort(__float2half_rn(d3));
                *(uint32_t*)(C16 + (size_t)r0 * ldc + col)       = h0 | ((uint32_t)h1 << 16);
                *(uint32_t*)(C16 + (size_t)(r0 + 8) * ldc + col) = h2 | ((uint32_t)h3 << 16);
            }
        }
    }
}

// ---------------------------------------------------------------------------
// Conversion kernels: fp32 -> fp16
// ---------------------------------------------------------------------------
__device__ __forceinline__ void hi4_store(float4 v, __half* dh, size_t i) {
    unsigned short h0 = __half_as_ushort(__float2half_rn(v.x));
    unsigned short h1 = __half_as_ushort(__float2half_rn(v.y));
    unsigned short h2 = __half_as_ushort(__float2half_rn(v.z));
    unsigned short h3 = __half_as_ushort(__float2half_rn(v.w));
    *(uint2*)(dh + i) = make_uint2(h0 | ((uint32_t)h1 << 16), h2 | ((uint32_t)h3 << 16));
}

__global__ __launch_bounds__(256) void k_conv_x(const float* __restrict__ x) {
    size_t i = ((size_t)blockIdx.x * 256 + threadIdx.x) * 4;
    hi4_store(*(const float4*)(x + i), g_x, i);
}

__global__ __launch_bounds__(256) void k_conv_w(const float* __restrict__ Wq,
                                                const float* __restrict__ Wk,
                                                const float* __restrict__ Wv) {
    const int z = blockIdx.z;
    const float* src = (z == 0) ? Wq : (z == 1) ? Wk : Wv;
    __half* dst = (z == 0) ? g_wq : (z == 1) ? g_wk : g_wv;
    size_t i = ((size_t)blockIdx.x * 256 + threadIdx.x) * 4;
    hi4_store(*(const float4*)(src + i), dst, i);
}

// ---------------------------------------------------------------------------
// GEMM wrappers (CTA tile 128x128)
// ---------------------------------------------------------------------------
// Q/K projection: C[token, out] = x @ W^T, fp16 out.
__global__ __launch_bounds__(256, 2) void k_proj_qk() {
    const int z = blockIdx.z;
    gemm128_nt(g_x, z ? g_wk : g_wq, DIMQ, DIMQ, DIMQ / 64,
               blockIdx.y * 128, blockIdx.x * 128, DIMQ,
               nullptr, z ? g_K : g_Q, 1.f, 2);
}

// Vt projection: Vt_b[v, token] = Wv @ x_b^T, fp16 out.
__global__ __launch_bounds__(256, 2) void k_proj_vt() {
    const int b = blockIdx.z;
    gemm128_nt(g_wv, g_x + (size_t)b * SEQB * DIMQ, DIMQ, DIMQ, DIMQ / 64,
               blockIdx.y * 128, blockIdx.x * 128, SEQB,
               nullptr, g_Vt + (size_t)b * DIMQ * SEQB, 1.f, 2);
}

// Scores: S_b = (Q_b @ K_b^T)/32, lower-tri blocks only, fp32 out.
__global__ __launch_bounds__(256, 2) void k_scores() {
    const int bn = blockIdx.x, bm = blockIdx.y, b = blockIdx.z;
    if (bn > bm) return;
    gemm128_nt(g_Q + (size_t)b * SEQB * DIMQ, g_K + (size_t)b * SEQB * DIMQ,
               DIMQ, DIMQ, DIMQ / 64, bm * 128, bn * 128, SEQB,
               g_S + (size_t)b * SEQB * SEQB, nullptr, 0.03125f, 0);
}

// Out: O_b = P_b @ Vt_b^T, K truncated at (bm+1)*128, fp32 out.
__global__ __launch_bounds__(256, 2) void k_out(float* __restrict__ out) {
    const int bn = blockIdx.x, bm = blockIdx.y, b = blockIdx.z;
    gemm128_nt(g_P + (size_t)b * SEQB * SEQB, g_Vt + (size_t)b * DIMQ * SEQB,
               SEQB, SEQB, (bm + 1) * 2, bm * 128, bn * 128, DIMQ,
               out + (size_t)b * SEQB * DIMQ, nullptr, 1.f, 0);
}

// ---------------------------------------------------------------------------
// Causal softmax: S fp32 row -> P fp16, zero-padded to 128 boundary
// ---------------------------------------------------------------------------
__global__ __launch_bounds__(256) void k_softmax() {
    const int i = blockIdx.x, b = blockIdx.y;
    const float* row = g_S + ((size_t)b * SEQB + i) * SEQB;
    __half* pr = g_P + ((size_t)b * SEQB + i) * SEQB;
    const int len = i + 1;
    const int t = threadIdx.x;

    float vals[8];
    float m = -1e30f;
#pragma unroll
    for (int k = 0; k < 8; k++) {
        int j = t + k * 256;
        float s = (j < len) ? row[j] : -1e30f;
        vals[k] = s;
        m = fmaxf(m, s);
    }
    __shared__ float red[256];
    red[t] = m;
    __syncthreads();
    for (int s = 128; s > 0; s >>= 1) {
        if (t < s) red[t] = fmaxf(red[t], red[t + s]);
        __syncthreads();
    }
    m = red[0];
    __syncthreads();

    float sum = 0.f;
#pragma unroll
    for (int k = 0; k < 8; k++) {
        int j = t + k * 256;
        if (j < len) { vals[k] = expf(vals[k] - m); sum += vals[k]; }
        else vals[k] = 0.f;
    }
    red[t] = sum;
    __syncthreads();
    for (int s = 128; s > 0; s >>= 1) {
        if (t < s) red[t] += red[t + s];
        __syncthreads();
    }
    const float inv = 1.0f / red[0];

    const int cap = (len + 127) & ~127;
#pragma unroll
    for (int k = 0; k < 8; k++) {
        int j = t + k * 256;
        if (j < cap) pr[j] = __float2half_rn(vals[k] * inv);
    }
}

// ---------------------------------------------------------------------------
extern "C" void kernel_launch(void* const* d_in, const int* in_sizes, int n_in,
                              void* d_out, int out_size)
{
    const float* x  = (const float*)d_in[0];
    const float* Wq = (const float*)d_in[1];
    const float* Wk = (const float*)d_in[2];
    const float* Wv = (const float*)d_in[3];
    float* out = (float*)d_out;

    cudaFuncSetAttribute(k_proj_qk, cudaFuncAttributeMaxDynamicSharedMemorySize, SMEM_SZ);
    cudaFuncSetAttribute(k_proj_vt, cudaFuncAttributeMaxDynamicSharedMemorySize, SMEM_SZ);
    cudaFuncSetAttribute(k_scores,  cudaFuncAttributeMaxDynamicSharedMemorySize, SMEM_SZ);
    cudaFuncSetAttribute(k_out,     cudaFuncAttributeMaxDynamicSharedMemorySize, SMEM_SZ);

    k_conv_x<<<(unsigned)(XE / 1024), 256>>>(x);
    k_conv_w<<<dim3((unsigned)(WE / 1024), 1, 3), 256>>>(Wq, Wk, Wv);

    k_proj_qk<<<dim3(DIMQ / 128, (NB * SEQB) / 128, 2), 256, SMEM_SZ>>>();   // (8,128,2)
    k_proj_vt<<<dim3(SEQB / 128, DIMQ / 128, NB), 256, SMEM_SZ>>>();         // (16,8,8)
    k_scores <<<dim3(SEQB / 128, SEQB / 128, NB), 256, SMEM_SZ>>>();         // (16,16,8)
    k_softmax<<<dim3(SEQB, NB), 256>>>();                                    // (2048,8)
    k_out    <<<dim3(DIMQ / 128, SEQB / 128, NB), 256, SMEM_SZ>>>(out);      // (8,16,8)
}

// round 14
// speedup vs baseline: 3.1316x; 1.0202x over previous
#include <cuda_runtime.h>
#include <cuda_fp16.h>
#include <stdint.h>
#include <math.h>

// Fixed problem dims
#define NB   8
#define SEQB 2048
#define DIMQ 1024

static constexpr size_t XE = (size_t)NB * SEQB * DIMQ;   // 16,777,216
static constexpr size_t WE = (size_t)DIMQ * DIMQ;        // 1,048,576
static constexpr size_t SE = (size_t)NB * SEQB * SEQB;   // 33,554,432

// Scratch (__device__ globals: allocation-free rule). All fp16.
__device__ __half g_x[XE];
__device__ __half g_wq[WE], g_wk[WE], g_wv[WE];
__device__ __half g_Q[XE], g_K[XE], g_Vt[XE];
__device__ __half g_E[SE];                   // exp(QK^T/32), unnormalized, causal-masked
__device__ float  g_inv[(size_t)NB * SEQB];  // 1 / row sums

// ---------------------------------------------------------------------------
// PTX helpers (baseline PTX only — no 'a'-gated features)
// ---------------------------------------------------------------------------
__device__ __forceinline__ uint32_t smem_u32(const void* p) {
    uint32_t a;
    asm("{ .reg .u64 t; cvta.to.shared.u64 t, %1; cvt.u32.u64 %0, t; }"
        : "=r"(a) : "l"(p));
    return a;
}

__device__ __forceinline__ void ldsm_x4(uint32_t addr, uint32_t& r0, uint32_t& r1,
                                        uint32_t& r2, uint32_t& r3) {
    asm volatile("ldmatrix.sync.aligned.m8n8.x4.shared.b16 {%0,%1,%2,%3}, [%4];"
                 : "=r"(r0), "=r"(r1), "=r"(r2), "=r"(r3) : "r"(addr));
}

__device__ __forceinline__ void mma16816(float& d0, float& d1, float& d2, float& d3,
                                         uint32_t a0, uint32_t a1, uint32_t a2, uint32_t a3,
                                         uint32_t b0, uint32_t b1) {
    asm volatile(
        "mma.sync.aligned.m16n8k16.row.col.f32.f16.f16.f32 "
        "{%0,%1,%2,%3}, {%4,%5,%6,%7}, {%8,%9}, {%0,%1,%2,%3};"
        : "+f"(d0), "+f"(d1), "+f"(d2), "+f"(d3)
        : "r"(a0), "r"(a1), "r"(a2), "r"(a3), "r"(b0), "r"(b1));
}

// ---------------------------------------------------------------------------
// GEMM-NT core, plain fp16: C[128,128] tile at (m0,n0) = sum_k A[m,k]*B[n,k]
// (fp32 accumulate). 256 threads = 8 warps (2m x 4n), warp tile 64x32,
// BK=64 (128B rows, SW128 swizzle), 3-stage cp.async ring, 2 CTAs/SM.
// Epilogue modes:
//   2: fp16 store                       (projections)
//   3: fp16 exp(d*alpha), causal mask   (scores -> E)
//   4: fp32 store d * inv[row]          (out, row-normalized)
// ---------------------------------------------------------------------------
#define STAGES  3
#define TILE_B  16384                       // 128 rows x 128 bytes
#define CHUNK_B (2 * TILE_B)                // A, B
#define SMEM_SZ (STAGES * CHUNK_B)          // 98304

__device__ __forceinline__ void gemm128_nt(
    const __half* __restrict__ A, const __half* __restrict__ B,
    int lda, int ldb, int kb64, int m0, int n0, int ldc,
    float* __restrict__ C32, __half* __restrict__ C16,
    const float* __restrict__ inv,
    float alpha, int mode)
{
    extern __shared__ char smem[];
    const uint32_t sbase = smem_u32(smem);
    const int tid  = threadIdx.x;
    const int wid  = tid >> 5;
    const int lane = tid & 31;
    const int wm = wid >> 2;      // 0..1 (64-row slab)
    const int wn = wid & 3;       // 0..3 (32-col slab)

    auto load_chunk = [&](int c, int s) {
        const int k0 = c * 64;
        const uint32_t st = sbase + s * CHUNK_B;
#pragma unroll
        for (int i = 0; i < 4; i++) {
            int o = tid + i * 256;            // 0..1023 : 128 rows x 8 x 16B
            int row = o >> 3, seg = o & 7;
            uint32_t off = (uint32_t)(o << 4);
            uint32_t sw = off ^ ((off >> 3) & 0x70);
            const __half* ga = A + (size_t)(m0 + row) * lda + k0 + seg * 8;
            const __half* gb = B + (size_t)(n0 + row) * ldb + k0 + seg * 8;
            asm volatile("cp.async.cg.shared.global [%0], [%1], 16;" :: "r"(st + sw),          "l"(ga));
            asm volatile("cp.async.cg.shared.global [%0], [%1], 16;" :: "r"(st + TILE_B + sw), "l"(gb));
        }
        asm volatile("cp.async.commit_group;" ::: "memory");
    };

    float acc[4][4][4];
#pragma unroll
    for (int i = 0; i < 4; i++)
#pragma unroll
        for (int j = 0; j < 4; j++)
#pragma unroll
            for (int k = 0; k < 4; k++) acc[i][j][k] = 0.f;

    // Prologue: 2 chunks in flight (kb64 >= 2 at all call sites)
    load_chunk(0, 0);
    load_chunk(1, 1);

    const int lrow = lane & 15;
    const int lhi  = (lane >> 4) & 1;

    for (int c = 0; c < kb64; c++) {
        const int s = c % STAGES;
        asm volatile("cp.async.wait_group 1;" ::: "memory");   // chunk c resident
        __syncthreads();

        const int nxt = c + 2;
        if (nxt < kb64) load_chunk(nxt, nxt % STAGES);
        else asm volatile("cp.async.commit_group;" ::: "memory");  // uniform counts

        const uint32_t st = sbase + s * CHUNK_B;
#pragma unroll
        for (int kk = 0; kk < 4; kk++) {
            const uint32_t col = (uint32_t)(kk * 32 + lhi * 16);   // byte column
            uint32_t a[4][4], b[2][4];
#pragma unroll
            for (int mf = 0; mf < 4; mf++) {
                int row = wm * 64 + mf * 16 + lrow;
                uint32_t addr = st + row * 128 + (col ^ ((row & 7) << 4));
                ldsm_x4(addr, a[mf][0], a[mf][1], a[mf][2], a[mf][3]);
            }
#pragma unroll
            for (int nf2 = 0; nf2 < 2; nf2++) {
                int row = wn * 32 + nf2 * 16 + lrow;
                uint32_t addr = st + TILE_B + row * 128 + (col ^ ((row & 7) << 4));
                ldsm_x4(addr, b[nf2][0], b[nf2][1], b[nf2][2], b[nf2][3]);
            }
#pragma unroll
            for (int mf = 0; mf < 4; mf++)
#pragma unroll
                for (int nf = 0; nf < 4; nf++) {
                    uint32_t h0 = (nf & 1) ? b[nf >> 1][1] : b[nf >> 1][0];
                    uint32_t h1 = (nf & 1) ? b[nf >> 1][3] : b[nf >> 1][2];
                    mma16816(acc[mf][nf][0], acc[mf][nf][1], acc[mf][nf][2], acc[mf][nf][3],
                             a[mf][0], a[mf][1], a[mf][2], a[mf][3], h0, h1);
                }
        }
    }

    // Epilogue: straight from registers.
#pragma unroll
    for (int mf = 0; mf < 4; mf++) {
#pragma unroll
        for (int nf = 0; nf < 4; nf++) {
            const int r0  = m0 + wm * 64 + mf * 16 + (lane >> 2);
            const int col = n0 + wn * 32 + nf * 8 + (lane & 3) * 2;
            float d0 = acc[mf][nf][0], d1 = acc[mf][nf][1];
            float d2 = acc[mf][nf][2], d3 = acc[mf][nf][3];
            if (mode == 2) {
                unsigned short h0 = __half_as_ushort(__float2half_rn(d0));
                unsigned short h1 = __half_as_ushort(__float2half_rn(d1));
                unsigned short h2 = __half_as_ushort(__float2half_rn(d2));
                unsigned short h3 = __half_as_ushort(__float2half_rn(d3));
                *(uint32_t*)(C16 + (size_t)r0 * ldc + col)       = h0 | ((uint32_t)h1 << 16);
                *(uint32_t*)(C16 + (size_t)(r0 + 8) * ldc + col) = h2 | ((uint32_t)h3 << 16);
            } else if (mode == 3) {
                // exp(score) with causal mask (col > row -> 0)
                float e0 = (col     <= r0    ) ? __expf(d0 * alpha) : 0.f;
                float e1 = (col + 1 <= r0    ) ? __expf(d1 * alpha) : 0.f;
                float e2 = (col     <= r0 + 8) ? __expf(d2 * alpha) : 0.f;
                float e3 = (col + 1 <= r0 + 8) ? __expf(d3 * alpha) : 0.f;
                unsigned short h0 = __half_as_ushort(__float2half_rn(e0));
                unsigned short h1 = __half_as_ushort(__float2half_rn(e1));
                unsigned short h2 = __half_as_ushort(__float2half_rn(e2));
                unsigned short h3 = __half_as_ushort(__float2half_rn(e3));
                *(uint32_t*)(C16 + (size_t)r0 * ldc + col)       = h0 | ((uint32_t)h1 << 16);
                *(uint32_t*)(C16 + (size_t)(r0 + 8) * ldc + col) = h2 | ((uint32_t)h3 << 16);
            } else {  // mode 4: fp32, row-normalized
                float iv0 = inv[r0];
                float iv1 = inv[r0 + 8];
                float2 u, v;
                u.x = d0 * iv0; u.y = d1 * iv0;
                v.x = d2 * iv1; v.y = d3 * iv1;
                *(float2*)(C32 + (size_t)r0 * ldc + col)       = u;
                *(float2*)(C32 + (size_t)(r0 + 8) * ldc + col) = v;
            }
        }
    }
}

// ---------------------------------------------------------------------------
// Conversion kernels: fp32 -> fp16
// ---------------------------------------------------------------------------
__device__ __forceinline__ void hi4_store(float4 v, __half* dh, size_t i) {
    unsigned short h0 = __half_as_ushort(__float2half_rn(v.x));
    unsigned short h1 = __half_as_ushort(__float2half_rn(v.y));
    unsigned short h2 = __half_as_ushort(__float2half_rn(v.z));
    unsigned short h3 = __half_as_ushort(__float2half_rn(v.w));
    *(uint2*)(dh + i) = make_uint2(h0 | ((uint32_t)h1 << 16), h2 | ((uint32_t)h3 << 16));
}

__global__ __launch_bounds__(256) void k_conv_x(const float* __restrict__ x) {
    size_t i = ((size_t)blockIdx.x * 256 + threadIdx.x) * 4;
    hi4_store(*(const float4*)(x + i), g_x, i);
}

__global__ __launch_bounds__(256) void k_conv_w(const float* __restrict__ Wq,
                                                const float* __restrict__ Wk,
                                                const float* __restrict__ Wv) {
    const int z = blockIdx.z;
    const float* src = (z == 0) ? Wq : (z == 1) ? Wk : Wv;
    __half* dst = (z == 0) ? g_wq : (z == 1) ? g_wk : g_wv;
    size_t i = ((size_t)blockIdx.x * 256 + threadIdx.x) * 4;
    hi4_store(*(const float4*)(src + i), dst, i);
}

// ---------------------------------------------------------------------------
// GEMM wrappers (CTA tile 128x128)
// ---------------------------------------------------------------------------
// Q/K projection: C[token, out] = x @ W^T, fp16 out.
__global__ __launch_bounds__(256, 2) void k_proj_qk() {
    const int z = blockIdx.z;
    gemm128_nt(g_x, z ? g_wk : g_wq, DIMQ, DIMQ, DIMQ / 64,
               blockIdx.y * 128, blockIdx.x * 128, DIMQ,
               nullptr, z ? g_K : g_Q, nullptr, 1.f, 2);
}

// Vt projection: Vt_b[v, token] = Wv @ x_b^T, fp16 out.
__global__ __launch_bounds__(256, 2) void k_proj_vt() {
    const int b = blockIdx.z;
    gemm128_nt(g_wv, g_x + (size_t)b * SEQB * DIMQ, DIMQ, DIMQ, DIMQ / 64,
               blockIdx.y * 128, blockIdx.x * 128, SEQB,
               nullptr, g_Vt + (size_t)b * DIMQ * SEQB, nullptr, 1.f, 2);
}

// Scores: E_b = exp((Q_b @ K_b^T)/32), causal-masked, fp16 out.
// Compacted grid: blockIdx.x = triangular tile index t in [0,136), batch = y.
__global__ __launch_bounds__(256, 2) void k_scores() {
    const int t = blockIdx.x, b = blockIdx.y;
    int bm = (int)((sqrtf(8.f * (float)t + 1.f) - 1.f) * 0.5f);
    if ((bm + 1) * (bm + 2) / 2 <= t) bm++;
    else if (bm * (bm + 1) / 2 > t) bm--;
    const int bn = t - bm * (bm + 1) / 2;
    gemm128_nt(g_Q + (size_t)b * SEQB * DIMQ, g_K + (size_t)b * SEQB * DIMQ,
               DIMQ, DIMQ, DIMQ / 64, bm * 128, bn * 128, SEQB,
               nullptr, g_E + (size_t)b * SEQB * SEQB, nullptr, 0.03125f, 3);
}

// Out: O_b = (E_b @ Vt_b^T) * inv[row], K truncated at (bm+1)*128, fp32 out.
__global__ __launch_bounds__(256, 2) void k_out(float* __restrict__ out) {
    const int bn = blockIdx.x, bm = blockIdx.y, b = blockIdx.z;
    gemm128_nt(g_E + (size_t)b * SEQB * SEQB, g_Vt + (size_t)b * DIMQ * SEQB,
               SEQB, SEQB, (bm + 1) * 2, bm * 128, bn * 128, DIMQ,
               out + (size_t)b * SEQB * DIMQ, nullptr,
               g_inv + (size_t)b * SEQB, 1.f, 4);
}

// ---------------------------------------------------------------------------
// Row sums of E (causal length), inv = 1/sum. grid (SEQB, NB), 256 threads.
// ---------------------------------------------------------------------------
__global__ __launch_bounds__(256) void k_rowsum() {
    const int i = blockIdx.x, b = blockIdx.y;
    const __half* row = g_E + ((size_t)b * SEQB + i) * SEQB;
    const int len = i + 1;
    const int t = threadIdx.x;

    float sum = 0.f;
    for (int j = t; j < len; j += 256) sum += __half2float(row[j]);

    __shared__ float red[256];
    red[t] = sum;
    __syncthreads();
    for (int s = 128; s > 0; s >>= 1) {
        if (t < s) red[t] += red[t + s];
        __syncthreads();
    }
    if (t == 0) g_inv[(size_t)b * SEQB + i] = 1.0f / red[0];
}

// ---------------------------------------------------------------------------
extern "C" void kernel_launch(void* const* d_in, const int* in_sizes, int n_in,
                              void* d_out, int out_size)
{
    const float* x  = (const float*)d_in[0];
    const float* Wq = (const float*)d_in[1];
    const float* Wk = (const float*)d_in[2];
    const float* Wv = (const float*)d_in[3];
    float* out = (float*)d_out;

    cudaFuncSetAttribute(k_proj_qk, cudaFuncAttributeMaxDynamicSharedMemorySize, SMEM_SZ);
    cudaFuncSetAttribute(k_proj_vt, cudaFuncAttributeMaxDynamicSharedMemorySize, SMEM_SZ);
    cudaFuncSetAttribute(k_scores,  cudaFuncAttributeMaxDynamicSharedMemorySize, SMEM_SZ);
    cudaFuncSetAttribute(k_out,     cudaFuncAttributeMaxDynamicSharedMemorySize, SMEM_SZ);

    k_conv_x<<<(unsigned)(XE / 1024), 256>>>(x);
    k_conv_w<<<dim3((unsigned)(WE / 1024), 1, 3), 256>>>(Wq, Wk, Wv);

    k_proj_qk<<<dim3(DIMQ / 128, (NB * SEQB) / 128, 2), 256, SMEM_SZ>>>();   // (8,128,2)
    k_proj_vt<<<dim3(SEQB / 128, DIMQ / 128, NB), 256, SMEM_SZ>>>();         // (16,8,8)
    k_scores <<<dim3(136, NB), 256, SMEM_SZ>>>();                            // 136 tri tiles x 8
    k_rowsum <<<dim3(SEQB, NB), 256>>>();                                    // (2048,8)
    k_out    <<<dim3(DIMQ / 128, SEQB / 128, NB), 256, SMEM_SZ>>>(out);      // (8,16,8)
}

// round 15
// speedup vs baseline: 3.3444x; 1.0680x over previous
#include <cuda_runtime.h>
#include <cuda_fp16.h>
#include <stdint.h>
#include <math.h>

// Fixed problem dims
#define NB   8
#define SEQB 2048
#define DIMQ 1024

static constexpr size_t XE = (size_t)NB * SEQB * DIMQ;   // 16,777,216
static constexpr size_t WE = (size_t)DIMQ * DIMQ;        // 1,048,576
static constexpr size_t SE = (size_t)NB * SEQB * SEQB;   // 33,554,432

// Scratch (__device__ globals: allocation-free rule). All fp16.
__device__ __half g_x[XE];
__device__ __half g_wq[WE], g_wk[WE], g_wv[WE];
__device__ __half g_Q[XE], g_K[XE], g_Vt[XE];
__device__ __half g_E[SE];                   // exp(QK^T/32), unnormalized, causal-masked
__device__ float  g_sum[(size_t)NB * SEQB];  // row sums (atomic-accumulated by scores)

// ---------------------------------------------------------------------------
// PTX helpers (baseline PTX only — no 'a'-gated features)
// ---------------------------------------------------------------------------
__device__ __forceinline__ uint32_t smem_u32(const void* p) {
    uint32_t a;
    asm("{ .reg .u64 t; cvta.to.shared.u64 t, %1; cvt.u32.u64 %0, t; }"
        : "=r"(a) : "l"(p));
    return a;
}

__device__ __forceinline__ void ldsm_x4(uint32_t addr, uint32_t& r0, uint32_t& r1,
                                        uint32_t& r2, uint32_t& r3) {
    asm volatile("ldmatrix.sync.aligned.m8n8.x4.shared.b16 {%0,%1,%2,%3}, [%4];"
                 : "=r"(r0), "=r"(r1), "=r"(r2), "=r"(r3) : "r"(addr));
}

__device__ __forceinline__ void mma16816(float& d0, float& d1, float& d2, float& d3,
                                         uint32_t a0, uint32_t a1, uint32_t a2, uint32_t a3,
                                         uint32_t b0, uint32_t b1) {
    asm volatile(
        "mma.sync.aligned.m16n8k16.row.col.f32.f16.f16.f32 "
        "{%0,%1,%2,%3}, {%4,%5,%6,%7}, {%8,%9}, {%0,%1,%2,%3};"
        : "+f"(d0), "+f"(d1), "+f"(d2), "+f"(d3)
        : "r"(a0), "r"(a1), "r"(a2), "r"(a3), "r"(b0), "r"(b1));
}

// ---------------------------------------------------------------------------
// GEMM-NT core, plain fp16: C[128,128] tile at (m0,n0) = sum_k A[m,k]*B[n,k]
// (fp32 accumulate). 256 threads = 8 warps (2m x 4n), warp tile 64x32,
// BK=64 (128B rows, SW128 swizzle), 3-stage cp.async ring, 2 CTAs/SM.
// Epilogue modes:
//   2: fp16 store                                    (projections)
//   3: fp16 exp(d*alpha), causal mask, atomic rowsum (scores -> E, g_sum)
//   4: fp32 store d / aux[row]                       (out, row-normalized)
// ---------------------------------------------------------------------------
#define STAGES  3
#define TILE_B  16384                       // 128 rows x 128 bytes
#define CHUNK_B (2 * TILE_B)                // A, B
#define SMEM_SZ (STAGES * CHUNK_B)          // 98304

__device__ __forceinline__ void gemm128_nt(
    const __half* __restrict__ A, const __half* __restrict__ B,
    int lda, int ldb, int kb64, int m0, int n0, int ldc,
    float* __restrict__ C32, __half* __restrict__ C16,
    float* __restrict__ aux,
    float alpha, int mode)
{
    extern __shared__ char smem[];
    const uint32_t sbase = smem_u32(smem);
    const int tid  = threadIdx.x;
    const int wid  = tid >> 5;
    const int lane = tid & 31;
    const int wm = wid >> 2;      // 0..1 (64-row slab)
    const int wn = wid & 3;       // 0..3 (32-col slab)

    auto load_chunk = [&](int c, int s) {
        const int k0 = c * 64;
        const uint32_t st = sbase + s * CHUNK_B;
#pragma unroll
        for (int i = 0; i < 4; i++) {
            int o = tid + i * 256;            // 0..1023 : 128 rows x 8 x 16B
            int row = o >> 3, seg = o & 7;
            uint32_t off = (uint32_t)(o << 4);
            uint32_t sw = off ^ ((off >> 3) & 0x70);
            const __half* ga = A + (size_t)(m0 + row) * lda + k0 + seg * 8;
            const __half* gb = B + (size_t)(n0 + row) * ldb + k0 + seg * 8;
            asm volatile("cp.async.cg.shared.global [%0], [%1], 16;" :: "r"(st + sw),          "l"(ga));
            asm volatile("cp.async.cg.shared.global [%0], [%1], 16;" :: "r"(st + TILE_B + sw), "l"(gb));
        }
        asm volatile("cp.async.commit_group;" ::: "memory");
    };

    float acc[4][4][4];
#pragma unroll
    for (int i = 0; i < 4; i++)
#pragma unroll
        for (int j = 0; j < 4; j++)
#pragma unroll
            for (int k = 0; k < 4; k++) acc[i][j][k] = 0.f;

    // Prologue: 2 chunks in flight (kb64 >= 2 at all call sites)
    load_chunk(0, 0);
    load_chunk(1, 1);

    const int lrow = lane & 15;
    const int lhi  = (lane >> 4) & 1;

    for (int c = 0; c < kb64; c++) {
        const int s = c % STAGES;
        asm volatile("cp.async.wait_group 1;" ::: "memory");   // chunk c resident
        __syncthreads();

        const int nxt = c + 2;
        if (nxt < kb64) load_chunk(nxt, nxt % STAGES);
        else asm volatile("cp.async.commit_group;" ::: "memory");  // uniform counts

        const uint32_t st = sbase + s * CHUNK_B;
#pragma unroll
        for (int kk = 0; kk < 4; kk++) {
            const uint32_t col = (uint32_t)(kk * 32 + lhi * 16);   // byte column
            uint32_t a[4][4], b[2][4];
#pragma unroll
            for (int mf = 0; mf < 4; mf++) {
                int row = wm * 64 + mf * 16 + lrow;
                uint32_t addr = st + row * 128 + (col ^ ((row & 7) << 4));
                ldsm_x4(addr, a[mf][0], a[mf][1], a[mf][2], a[mf][3]);
            }
#pragma unroll
            for (int nf2 = 0; nf2 < 2; nf2++) {
                int row = wn * 32 + nf2 * 16 + lrow;
                uint32_t addr = st + TILE_B + row * 128 + (col ^ ((row & 7) << 4));
                ldsm_x4(addr, b[nf2][0], b[nf2][1], b[nf2][2], b[nf2][3]);
            }
#pragma unroll
            for (int mf = 0; mf < 4; mf++)
#pragma unroll
                for (int nf = 0; nf < 4; nf++) {
                    uint32_t h0 = (nf & 1) ? b[nf >> 1][1] : b[nf >> 1][0];
                    uint32_t h1 = (nf & 1) ? b[nf >> 1][3] : b[nf >> 1][2];
                    mma16816(acc[mf][nf][0], acc[mf][nf][1], acc[mf][nf][2], acc[mf][nf][3],
                             a[mf][0], a[mf][1], a[mf][2], a[mf][3], h0, h1);
                }
        }
    }

    // Epilogue: straight from registers.
#pragma unroll
    for (int mf = 0; mf < 4; mf++) {
        float rs0 = 0.f, rs1 = 0.f;   // mode-3 row-sum partials (rows r0, r0+8)
#pragma unroll
        for (int nf = 0; nf < 4; nf++) {
            const int r0  = m0 + wm * 64 + mf * 16 + (lane >> 2);
            const int col = n0 + wn * 32 + nf * 8 + (lane & 3) * 2;
            float d0 = acc[mf][nf][0], d1 = acc[mf][nf][1];
            float d2 = acc[mf][nf][2], d3 = acc[mf][nf][3];
            if (mode == 2) {
                unsigned short h0 = __half_as_ushort(__float2half_rn(d0));
                unsigned short h1 = __half_as_ushort(__float2half_rn(d1));
                unsigned short h2 = __half_as_ushort(__float2half_rn(d2));
                unsigned short h3 = __half_as_ushort(__float2half_rn(d3));
                *(uint32_t*)(C16 + (size_t)r0 * ldc + col)       = h0 | ((uint32_t)h1 << 16);
                *(uint32_t*)(C16 + (size_t)(r0 + 8) * ldc + col) = h2 | ((uint32_t)h3 << 16);
            } else if (mode == 3) {
                // exp(score) with causal mask (col > row -> 0); accumulate row sums
                float e0 = (col     <= r0    ) ? __expf(d0 * alpha) : 0.f;
                float e1 = (col + 1 <= r0    ) ? __expf(d1 * alpha) : 0.f;
                float e2 = (col     <= r0 + 8) ? __expf(d2 * alpha) : 0.f;
                float e3 = (col + 1 <= r0 + 8) ? __expf(d3 * alpha) : 0.f;
                rs0 += e0 + e1;
                rs1 += e2 + e3;
                unsigned short h0 = __half_as_ushort(__float2half_rn(e0));
                unsigned short h1 = __half_as_ushort(__float2half_rn(e1));
                unsigned short h2 = __half_as_ushort(__float2half_rn(e2));
                unsigned short h3 = __half_as_ushort(__float2half_rn(e3));
                *(uint32_t*)(C16 + (size_t)r0 * ldc + col)       = h0 | ((uint32_t)h1 << 16);
                *(uint32_t*)(C16 + (size_t)(r0 + 8) * ldc + col) = h2 | ((uint32_t)h3 << 16);
            } else {  // mode 4: fp32, row-normalized by aux[row]
                float iv0 = __fdividef(1.f, aux[r0]);
                float iv1 = __fdividef(1.f, aux[r0 + 8]);
                float2 u, v;
                u.x = d0 * iv0; u.y = d1 * iv0;
                v.x = d2 * iv1; v.y = d3 * iv1;
                *(float2*)(C32 + (size_t)r0 * ldc + col)       = u;
                *(float2*)(C32 + (size_t)(r0 + 8) * ldc + col) = v;
            }
        }
        if (mode == 3) {
            // lanes 4k..4k+3 share the same rows; quad-reduce then one atomic
            rs0 += __shfl_xor_sync(0xFFFFFFFF, rs0, 1);
            rs0 += __shfl_xor_sync(0xFFFFFFFF, rs0, 2);
            rs1 += __shfl_xor_sync(0xFFFFFFFF, rs1, 1);
            rs1 += __shfl_xor_sync(0xFFFFFFFF, rs1, 2);
            if ((lane & 3) == 0) {
                const int r0 = m0 + wm * 64 + mf * 16 + (lane >> 2);
                atomicAdd(aux + r0,     rs0);
                atomicAdd(aux + r0 + 8, rs1);
            }
        }
    }
}

// ---------------------------------------------------------------------------
// Conversion kernels: fp32 -> fp16
// ---------------------------------------------------------------------------
__device__ __forceinline__ void hi4_store(float4 v, __half* dh, size_t i) {
    unsigned short h0 = __half_as_ushort(__float2half_rn(v.x));
    unsigned short h1 = __half_as_ushort(__float2half_rn(v.y));
    unsigned short h2 = __half_as_ushort(__float2half_rn(v.z));
    unsigned short h3 = __half_as_ushort(__float2half_rn(v.w));
    *(uint2*)(dh + i) = make_uint2(h0 | ((uint32_t)h1 << 16), h2 | ((uint32_t)h3 << 16));
}

__global__ __launch_bounds__(256) void k_zero_sum() {
    size_t i = (size_t)blockIdx.x * 1024 + threadIdx.x * 4;
    *(float4*)(g_sum + i) = make_float4(0.f, 0.f, 0.f, 0.f);
}

__global__ __launch_bounds__(256) void k_conv_x(const float* __restrict__ x) {
    size_t i = ((size_t)blockIdx.x * 256 + threadIdx.x) * 4;
    hi4_store(*(const float4*)(x + i), g_x, i);
}

__global__ __launch_bounds__(256) void k_conv_w(const float* __restrict__ Wq,
                                                const float* __restrict__ Wk,
                                                const float* __restrict__ Wv) {
    const int z = blockIdx.z;
    const float* src = (z == 0) ? Wq : (z == 1) ? Wk : Wv;
    __half* dst = (z == 0) ? g_wq : (z == 1) ? g_wk : g_wv;
    size_t i = ((size_t)blockIdx.x * 256 + threadIdx.x) * 4;
    hi4_store(*(const float4*)(src + i), dst, i);
}

// ---------------------------------------------------------------------------
// Merged projections: 1D grid of 3072 CTAs.
//   id in [0,2048): Q/K proj  (z = id>>10, tile = id & 1023 -> 128x8 tiles)
//   id in [2048,3072): Vt proj (per-batch 16x8 tiles)
// ---------------------------------------------------------------------------
__global__ __launch_bounds__(256, 2) void k_proj() {
    const int id = blockIdx.x;
    if (id < 2048) {
        const int z   = id >> 10;
        const int rem = id & 1023;
        const int by  = rem >> 3;       // 0..127 (token tiles)
        const int bx  = rem & 7;        // 0..7   (out-dim tiles)
        gemm128_nt(g_x, z ? g_wk : g_wq, DIMQ, DIMQ, DIMQ / 64,
                   by * 128, bx * 128, DIMQ,
                   nullptr, z ? g_K : g_Q, nullptr, 1.f, 2);
    } else {
        const int id2 = id - 2048;
        const int b   = id2 >> 7;       // 0..7
        const int rem = id2 & 127;
        const int bx  = rem & 15;       // 0..15 (token tiles)
        const int by  = rem >> 4;       // 0..7  (v-dim tiles)
        gemm128_nt(g_wv, g_x + (size_t)b * SEQB * DIMQ, DIMQ, DIMQ, DIMQ / 64,
                   by * 128, bx * 128, SEQB,
                   nullptr, g_Vt + (size_t)b * DIMQ * SEQB, nullptr, 1.f, 2);
    }
}

// Scores: E_b = exp((Q_b @ K_b^T)/32), causal-masked, fp16 out + atomic rowsums.
// Compacted grid: blockIdx.x = triangular tile index t in [0,136), batch = y.
__global__ __launch_bounds__(256, 2) void k_scores() {
    const int t = blockIdx.x, b = blockIdx.y;
    int bm = (int)((sqrtf(8.f * (float)t + 1.f) - 1.f) * 0.5f);
    if ((bm + 1) * (bm + 2) / 2 <= t) bm++;
    else if (bm * (bm + 1) / 2 > t) bm--;
    const int bn = t - bm * (bm + 1) / 2;
    gemm128_nt(g_Q + (size_t)b * SEQB * DIMQ, g_K + (size_t)b * SEQB * DIMQ,
               DIMQ, DIMQ, DIMQ / 64, bm * 128, bn * 128, SEQB,
               nullptr, g_E + (size_t)b * SEQB * SEQB,
               g_sum + (size_t)b * SEQB, 0.03125f, 3);
}

// Out: O_b = (E_b @ Vt_b^T) / sum[row], K truncated at (bm+1)*128.
// bm reversed so the longest-K CTAs launch first (better wave packing).
__global__ __launch_bounds__(256, 2) void k_out(float* __restrict__ out) {
    const int bn = blockIdx.x, bm = 15 - blockIdx.y, b = blockIdx.z;
    gemm128_nt(g_E + (size_t)b * SEQB * SEQB, g_Vt + (size_t)b * DIMQ * SEQB,
               SEQB, SEQB, (bm + 1) * 2, bm * 128, bn * 128, DIMQ,
               out + (size_t)b * SEQB * DIMQ, nullptr,
               g_sum + (size_t)b * SEQB, 1.f, 4);
}

// ---------------------------------------------------------------------------
extern "C" void kernel_launch(void* const* d_in, const int* in_sizes, int n_in,
                              void* d_out, int out_size)
{
    const float* x  = (const float*)d_in[0];
    const float* Wq = (const float*)d_in[1];
    const float* Wk = (const float*)d_in[2];
    const float* Wv = (const float*)d_in[3];
    float* out = (float*)d_out;

    cudaFuncSetAttribute(k_proj,   cudaFuncAttributeMaxDynamicSharedMemorySize, SMEM_SZ);
    cudaFuncSetAttribute(k_scores, cudaFuncAttributeMaxDynamicSharedMemorySize, SMEM_SZ);
    cudaFuncSetAttribute(k_out,    cudaFuncAttributeMaxDynamicSharedMemorySize, SMEM_SZ);

    k_zero_sum<<<(NB * SEQB) / 1024, 256>>>();
    k_conv_x<<<(unsigned)(XE / 1024), 256>>>(x);
    k_conv_w<<<dim3((unsigned)(WE / 1024), 1, 3), 256>>>(Wq, Wk, Wv);

    k_proj  <<<3072, 256, SMEM_SZ>>>();                                  // merged QK + Vt
    k_scores<<<dim3(136, NB), 256, SMEM_SZ>>>();                         // 136 tri tiles x 8
    k_out   <<<dim3(DIMQ / 128, SEQB / 128, NB), 256, SMEM_SZ>>>(out);   // (8,16,8)
}